// round 6
// baseline (speedup 1.0000x reference)
#include <cuda_runtime.h>
#include <cuda_bf16.h>
#include <cstdint>

#define Tt 3
#define Ll 4
#define Mm 3
#define Bb 8
#define Cc 64
#define Hh 128
#define Ww 128
#define HWp (Hh*Ww)
#define PW 130
#define PPX (PW*PW)              // 16900 padded pixels
#define FRONT 256
#define SLACK 384
#define PTOT (FRONT + PPX + SLACK)

#define TILE_M 256
#define HALO 131                 // PW + 1
#define STRIP_PX (TILE_M + 2*HALO)   // 518
#define CHUNK_B (STRIP_PX*32)        // 16576 bytes: 518 px x 16 ic x 2B
#define TILES 67                 // ceil(PPX/TILE_M)
#define CTAS 148
#define JOBS (Tt*Bb*TILES)       // 1608 jobs per layer

#define SW_OFF 0                 // weights: 9 taps x 2 halves x 8192 B = 147456
#define SA_OFF 147456            // A rings: [Ah0,Ah1,Al0,Al1] x 16576 = 66304
#define DBUF_OFF (SA_OFF + 4*CHUNK_B)  // 213760
#define SMEM_TOT (DBUF_OFF + 6144)     // 219904

// ---------------- device state ----------------
__device__ int g_sel[Tt*Ll];
// weights bf16: [mod 12][tap 9][half 2][oc 64][ic 64]
__device__ __align__(256) __nv_bfloat16 g_wB[(size_t)12*9*2*64*64];
// layer-0 input, padded NHWC bf16: [half][b][PTOT][64]
__device__ __align__(256) __nv_bfloat16 g_xp[2][(size_t)Bb*PTOT*Cc];
// ping-pong activations: [pp 2][half 2][t*b 24][PTOT][64]
__device__ __align__(256) __nv_bfloat16 g_act[2][2][(size_t)Tt*Bb*PTOT*Cc];

// ---------------- helpers ----------------
__device__ __forceinline__ uint32_t smem_u32(const void* p) {
    uint32_t a;
    asm("{ .reg .u64 t; cvta.to.shared.u64 t, %1; cvt.u32.u64 %0, t; }" : "=r"(a) : "l"(p));
    return a;
}
__device__ __forceinline__ void cp16(uint32_t sdst, const void* gsrc) {
    asm volatile("cp.async.cg.shared.global [%0], [%1], 16;" :: "r"(sdst), "l"(gsrc) : "memory");
}
__device__ __forceinline__ void cp_commit() { asm volatile("cp.async.commit_group;" ::: "memory"); }
template <int N>
__device__ __forceinline__ void cp_wait() {
    asm volatile("cp.async.wait_group %0;" :: "n"(N) : "memory");
}

__device__ __forceinline__ void ldmx4(uint32_t* r, uint32_t addr) {
    asm volatile("ldmatrix.sync.aligned.m8n8.x4.shared.b16 {%0,%1,%2,%3}, [%4];"
                 : "=r"(r[0]), "=r"(r[1]), "=r"(r[2]), "=r"(r[3]) : "r"(addr));
}
__device__ __forceinline__ void mma16816(float* c, const uint32_t* a, const uint32_t* b) {
    asm volatile("mma.sync.aligned.m16n8k16.row.col.f32.bf16.bf16.f32 "
                 "{%0,%1,%2,%3}, {%4,%5,%6,%7}, {%8,%9}, {%0,%1,%2,%3};"
                 : "+f"(c[0]), "+f"(c[1]), "+f"(c[2]), "+f"(c[3])
                 : "r"(a[0]), "r"(a[1]), "r"(a[2]), "r"(a[3]), "r"(b[0]), "r"(b[1]));
}

// ---------------- fused prep kernel ----------------------------------------
// blocks [0,128): xprep (4 px/thread); [128,1856): wprep; [1856,2362): border
// zero; block 2362: routing.
__global__ void __launch_bounds__(256) prep_kernel(
    const float* __restrict__ x, const float* __restrict__ alpha0,
    const float* __restrict__ alphas, const float* __restrict__ g0,
    const float* __restrict__ gs, const float* __restrict__ enc_w)
{
    const int bid = blockIdx.x;
    const int tid = threadIdx.x;

    if (bid < 128) {
        // ---- xprep: NCHW fp32 -> padded NHWC bf16 hi/lo, 4 px per thread ----
        int idx = bid * 256 + tid;            // [0, 32768)
        int b = idx >> 12;
        int pg = idx & 4095;
        int px0 = pg * 4;
        int y = px0 >> 7, x0 = px0 & 127;
        int p0 = (y + 1) * PW + (x0 + 1);
        const float* xs = x + ((size_t)b * Cc << 14) + px0;
        __nv_bfloat16* dh = g_xp[0] + ((size_t)b * PTOT + FRONT + p0) * Cc;
        __nv_bfloat16* dl = g_xp[1] + ((size_t)b * PTOT + FRONT + p0) * Cc;
        #pragma unroll
        for (int g = 0; g < 8; g++) {
            float4 v[8];
            #pragma unroll
            for (int j = 0; j < 8; j++)
                v[j] = *reinterpret_cast<const float4*>(xs + (size_t)(g*8 + j) * HWp);
            #pragma unroll
            for (int e = 0; e < 4; e++) {
                uint32_t hv[4], lv[4];
                #pragma unroll
                for (int q = 0; q < 4; q++) {
                    float f0 = (&v[q*2].x)[e];
                    float f1 = (&v[q*2+1].x)[e];
                    __nv_bfloat16 h0 = __float2bfloat16(f0);
                    __nv_bfloat16 h1 = __float2bfloat16(f1);
                    __nv_bfloat16 l0 = __float2bfloat16(f0 - __bfloat162float(h0));
                    __nv_bfloat16 l1 = __float2bfloat16(f1 - __bfloat162float(h1));
                    // interleave: ic pair (g*8+2q, g*8+2q+1)
                    hv[q] = (uint32_t)__bfloat16_as_ushort(h1) << 16 | __bfloat16_as_ushort(h0);
                    lv[q] = (uint32_t)__bfloat16_as_ushort(l1) << 16 | __bfloat16_as_ushort(l0);
                }
                *reinterpret_cast<uint4*>(dh + (size_t)e * Cc + g*8) =
                    make_uint4(hv[0], hv[1], hv[2], hv[3]);
                *reinterpret_cast<uint4*>(dl + (size_t)e * Cc + g*8) =
                    make_uint4(lv[0], lv[1], lv[2], lv[3]);
            }
        }
    } else if (bid < 1856) {
        // ---- wprep: OIHW fp32 -> [mod][tap][half][oc][ic] bf16 ----
        int i = (bid - 128) * 256 + tid;       // [0, 442368)
        int ic  = i & 63;
        int oc  = (i >> 6) & 63;
        int tap = (i >> 12) % 9;
        int mod = i / 36864;
        float w = enc_w[(((size_t)(mod*Cc + oc))*Cc + ic)*9 + tap];
        __nv_bfloat16 hi = __float2bfloat16(w);
        __nv_bfloat16 lo = __float2bfloat16(w - __bfloat162float(hi));
        size_t base = (((size_t)mod*9 + tap)*2) * 4096 + oc*64 + ic;
        g_wB[base] = hi;
        g_wB[base + 4096] = lo;
    } else if (bid < 2362) {
        // ---- zero border pixels of all 112 padded planes ----
        int item = (bid - 1856) * 256 + tid;
        if (item >= 112 * 1156) return;
        int plane = item / 1156;
        int bi = item - plane * 1156;
        int px;
        if (bi < 256) px = bi;
        else {
            bi -= 256;
            if (bi < 130) px = FRONT + bi;
            else {
                bi -= 130;
                if (bi < 256) { int r = bi >> 1, c = bi & 1; px = FRONT + (r+1)*PW + c*129; }
                else {
                    bi -= 256;
                    if (bi < 130) px = FRONT + 129*PW + bi;
                    else px = FRONT + PPX + (bi - 130);
                }
            }
        }
        __nv_bfloat16* base;
        if (plane < 16) base = g_xp[plane >> 3] + (size_t)(plane & 7) * PTOT * Cc;
        else {
            int k = plane - 16; int arr = k / 24; int img = k % 24;
            base = g_act[arr >> 1][arr & 1] + (size_t)img * PTOT * Cc;
        }
        uint4 z = make_uint4(0, 0, 0, 0);
        uint4* d = (uint4*)(base + (size_t)px * Cc);
        #pragma unroll
        for (int q = 0; q < 8; q++) d[q] = z;
    } else {
        // ---- routing ----
        int t = tid;
        if (t >= Tt) return;
        int idx = 0;
        {
            float best = -1e30f; int bi2 = 0;
            #pragma unroll
            for (int m = 0; m < Mm; m++) {
                float v = alpha0[t*Mm + m] + g0[t*Mm + m];
                if (v > best) { best = v; bi2 = m; }
            }
            idx = bi2; g_sel[t*Ll + 0] = bi2;
        }
        for (int l = 1; l < Ll; l++) {
            const float* a = alphas + ((((size_t)(l-1)*Tt + t)*Mm + idx)*Mm);
            const float* g = gs     + ((((size_t)(l-1)*Tt + t)*Mm + idx)*Mm);
            float best = -1e30f; int bi2 = 0;
            #pragma unroll
            for (int m = 0; m < Mm; m++) {
                float v = a[m] + g[m];
                if (v > best) { best = v; bi2 = m; }
            }
            idx = bi2; g_sel[t*Ll + l] = bi2;
        }
    }
}

// ---------------- conv layer kernel (k-chunk streamed A) --------------------
__global__ void __launch_bounds__(256) conv_hmma(
    int layer, int l0, int ps, int pd,
    const float* __restrict__ enc_b,
    const float* __restrict__ dec_w, const float* __restrict__ dec_b,
    float* __restrict__ out)
{
    extern __shared__ __align__(1024) char smem[];
    const uint32_t sb = smem_u32(smem);
    float (*dbuf)[2][3] = (float (*)[2][3])(smem + DBUF_OFF);
    const int tid = threadIdx.x;
    const int lane = tid & 31, wid = tid >> 5;
    const int wm = wid >> 1, wn = wid & 1;
    const int cta = blockIdx.x;

    // contiguous job partition: JOBS=1608 over 148 CTAs (q=10, r=128)
    const int nj = (cta < 128) ? 11 : 10;
    int j = (cta < 128) ? cta * 11 : 128 * 11 + (cta - 128) * 10;

    auto src_half = [&](int half, int img) -> const char* {
        const __nv_bfloat16* p;
        if (l0) p = g_xp[half] + ((size_t)(img & 7) * PTOT + FRONT) * Cc;
        else    p = g_act[ps][half] + ((size_t)img * PTOT + FRONT) * Cc;
        return (const char*)p;
    };
    // stage one k-chunk (hi+lo) of strip starting at (tb-HALO)
    auto stage_chunk = [&](int kc, int slot, const char* sH, const char* sL) {
        uint32_t dA = sb + SA_OFF + slot * CHUNK_B;
        uint32_t dB = dA + 2 * CHUNK_B;
        int ko = kc * 32;
        for (int i = tid; i < 2 * STRIP_PX; i += 256) {
            int px = i >> 1;
            int c = (i & 1) << 4;
            uint32_t sw = px * 32 + (uint32_t)(c ^ (((px >> 2) & 1) << 4));
            size_t go = (size_t)px * 128 + ko + c;
            cp16(dA + sw, sH + go);
            cp16(dB + sw, sL + go);
        }
    };
    auto stage_w = [&](int mod) {
        const char* wsrc = (const char*)g_wB + (size_t)mod * 147456;
        for (int g = tid; g < 9216; g += 256) {
            int tile = g >> 9;
            int o = (g & 511) * 16;
            int sw = o ^ ((o >> 3) & 0x70);
            cp16(sb + SW_OFF + tile * 8192 + sw, wsrc + tile * 8192 + o);
        }
    };

    // ---- fragment index precompute ----
    const int arow = lane & 15;
    const int acol = (lane >> 4) << 4;        // 0 or 16 within 32-B k-row
    const int ocl = (lane & 7) + ((lane >> 4) << 3);
    const int bkhalf = ((lane >> 3) & 1) * 16;
    int obase[2], oxor[2];
    #pragma unroll
    for (int pr = 0; pr < 2; pr++) {
        int oc = wn * 32 + pr * 16 + ocl;
        obase[pr] = oc * 128;
        oxor[pr] = (oc & 7) << 4;
    }

    // first tile: stage weights + chunk0
    {
        const int img0 = j / TILES;
        const int tile0 = j - img0 * TILES;
        const int t0 = img0 >> 3;
        const int mod0 = layer * Mm + g_sel[t0*Ll + layer];
        stage_w(mod0);
        const char* sH = src_half(0, img0) + (size_t)(tile0*TILE_M - HALO) * 128;
        const char* sL = src_half(1, img0) + (size_t)(tile0*TILE_M - HALO) * 128;
        stage_chunk(0, 0, sH, sL);
        cp_commit();
    }
    int cur_mod_t = (j / TILES) >> 3;   // task of staged weights

    for (int jj = 0; jj < nj; jj++, j++) {
        const int img = j / TILES;
        const int tile = j - img * TILES;
        const int t = img >> 3;
        const int tb = tile * TILE_M;
        const int mod = layer * Mm + g_sel[t*Ll + layer];
        const char* sH = src_half(0, img) + (size_t)(tb - HALO) * 128;
        const char* sL = src_half(1, img) + (size_t)(tb - HALO) * 128;

        // next-tile info
        bool has_next = (jj + 1 < nj);
        int img2 = 0, tb2 = 0, t2 = 0;
        bool mod_sw = false;
        const char* nH = nullptr; const char* nL = nullptr;
        if (has_next) {
            int j2 = j + 1;
            img2 = j2 / TILES;
            tb2 = (j2 - img2 * TILES) * TILE_M;
            t2 = img2 >> 3;
            mod_sw = (t2 != cur_mod_t) &&
                     (g_sel[t2*Ll + layer] != g_sel[cur_mod_t*Ll + layer]);
            nH = src_half(0, img2) + (size_t)(tb2 - HALO) * 128;
            nL = src_half(1, img2) + (size_t)(tb2 - HALO) * 128;
        }

        float acc[4][4][4];
        #pragma unroll
        for (int mt = 0; mt < 4; mt++)
            #pragma unroll
            for (int nt = 0; nt < 4; nt++)
                #pragma unroll
                for (int r = 0; r < 4; r++) acc[mt][nt][r] = 0.f;

        for (int k = 0; k < 4; k++) {
            __syncthreads();                        // all warps done k-1
            bool staged = false;
            if (k < 3) { stage_chunk(k + 1, (k + 1) & 1, sH, sL); staged = true; }
            else if (has_next && !mod_sw) { stage_chunk(0, 0, nH, nL); staged = true; }
            if (staged) { cp_commit(); cp_wait<1>(); } else { cp_wait<0>(); }
            __syncthreads();                        // chunk k visible

            const uint32_t aHb = sb + SA_OFF + (k & 1) * CHUNK_B;
            const int kb = k * 32 + bkhalf;

            #pragma unroll
            for (int tap = 0; tap < 9; tap++) {
                const int dy = tap / 3 - 1, dx = tap % 3 - 1;
                const int pxoff = HALO + dy * PW + dx;
                const uint32_t bbh = sb + SW_OFF + tap * 16384;

                uint32_t bh[4][2], bl[4][2];
                #pragma unroll
                for (int pr = 0; pr < 2; pr++) {
                    uint32_t off = obase[pr] + (uint32_t)(kb ^ oxor[pr]);
                    uint32_t r[4];
                    ldmx4(r, bbh + off);
                    bh[pr*2][0] = r[0]; bh[pr*2][1] = r[1];
                    bh[pr*2+1][0] = r[2]; bh[pr*2+1][1] = r[3];
                    ldmx4(r, bbh + 8192 + off);
                    bl[pr*2][0] = r[0]; bl[pr*2][1] = r[1];
                    bl[pr*2+1][0] = r[2]; bl[pr*2+1][1] = r[3];
                }
                uint32_t aH[4][4], aL[4][4];
                #pragma unroll
                for (int mt = 0; mt < 4; mt++) {
                    int px = wm * 64 + mt * 16 + arow + pxoff;
                    uint32_t sw = px * 32 + (uint32_t)(acol ^ (((px >> 2) & 1) << 4));
                    ldmx4(aH[mt], aHb + sw);
                    ldmx4(aL[mt], aHb + 2 * CHUNK_B + sw);
                }
                #pragma unroll
                for (int mt = 0; mt < 4; mt++)
                    #pragma unroll
                    for (int nt = 0; nt < 4; nt++) {
                        mma16816(acc[mt][nt], aH[mt], bh[nt]);
                        mma16816(acc[mt][nt], aH[mt], bl[nt]);
                        mma16816(acc[mt][nt], aL[mt], bh[nt]);
                    }
            }
        }

        const int g = lane >> 2, c2 = (lane & 3) * 2;
        const float* bb = enc_b + mod * 64;

        if (layer != 3) {
            __nv_bfloat16* dst_h = g_act[pd][0] + ((size_t)img * PTOT + FRONT) * Cc;
            __nv_bfloat16* dst_l = g_act[pd][1] + ((size_t)img * PTOT + FRONT) * Cc;
            #pragma unroll
            for (int mt = 0; mt < 4; mt++) {
                #pragma unroll
                for (int r = 0; r < 2; r++) {
                    int row = wm * 64 + mt * 16 + g + r * 8;
                    int p = tb + row;
                    if (p < PPX) {
                        int y = p / PW, xx = p - y * PW;
                        if (y >= 1 && y <= Hh && xx >= 1 && xx <= Ww) {
                            size_t base = (size_t)p * Cc;
                            #pragma unroll
                            for (int nt = 0; nt < 4; nt++) {
                                int oc = wn * 32 + nt * 8 + c2;
                                float f0 = fmaxf(acc[mt][nt][r*2+0] + __ldg(bb + oc),     0.f);
                                float f1 = fmaxf(acc[mt][nt][r*2+1] + __ldg(bb + oc + 1), 0.f);
                                __nv_bfloat16 h0 = __float2bfloat16(f0);
                                __nv_bfloat16 h1 = __float2bfloat16(f1);
                                __nv_bfloat16 l0 = __float2bfloat16(f0 - __bfloat162float(h0));
                                __nv_bfloat16 l1 = __float2bfloat16(f1 - __bfloat162float(h1));
                                uint32_t hw = (uint32_t)__bfloat16_as_ushort(h1) << 16 | __bfloat16_as_ushort(h0);
                                uint32_t lw = (uint32_t)__bfloat16_as_ushort(l1) << 16 | __bfloat16_as_ushort(l0);
                                *(uint32_t*)(dst_h + base + oc) = hw;
                                *(uint32_t*)(dst_l + base + oc) = lw;
                            }
                        }
                    }
                }
            }
        } else {
            // fused decoder
            float wd[3][8];
            #pragma unroll
            for (int kk = 0; kk < 3; kk++)
                #pragma unroll
                for (int q = 0; q < 8; q++) {
                    int oc = wn * 32 + (q >> 1) * 8 + c2 + (q & 1);
                    wd[kk][q] = __ldg(dec_w + ((size_t)t * 3 + kk) * 64 + oc);
                }
            #pragma unroll
            for (int mt = 0; mt < 4; mt++) {
                #pragma unroll
                for (int r = 0; r < 2; r++) {
                    float p0 = 0.f, p1 = 0.f, p2 = 0.f;
                    #pragma unroll
                    for (int nt = 0; nt < 4; nt++) {
                        int oc = wn * 32 + nt * 8 + c2;
                        float f0 = fmaxf(acc[mt][nt][r*2+0] + __ldg(bb + oc),     0.f);
                        float f1 = fmaxf(acc[mt][nt][r*2+1] + __ldg(bb + oc + 1), 0.f);
                        p0 = fmaf(f0, wd[0][nt*2+0], fmaf(f1, wd[0][nt*2+1], p0));
                        p1 = fmaf(f0, wd[1][nt*2+0], fmaf(f1, wd[1][nt*2+1], p1));
                        p2 = fmaf(f0, wd[2][nt*2+0], fmaf(f1, wd[2][nt*2+1], p2));
                    }
                    #pragma unroll
                    for (int off = 1; off < 4; off <<= 1) {
                        p0 += __shfl_xor_sync(0xffffffffu, p0, off);
                        p1 += __shfl_xor_sync(0xffffffffu, p1, off);
                        p2 += __shfl_xor_sync(0xffffffffu, p2, off);
                    }
                    if ((lane & 3) == 0) {
                        int pix = wm * 64 + mt * 16 + r * 8 + g;
                        dbuf[pix][wn][0] = p0;
                        dbuf[pix][wn][1] = p1;
                        dbuf[pix][wn][2] = p2;
                    }
                }
            }
            __syncthreads();
            {
                int p = tb + tid;
                if (p < PPX) {
                    int y = p / PW, xx = p - y * PW;
                    if (y >= 1 && y <= Hh && xx >= 1 && xx <= Ww) {
                        float a0 = dbuf[tid][0][0] + dbuf[tid][1][0] + __ldg(dec_b + t*3 + 0);
                        float a1 = dbuf[tid][0][1] + dbuf[tid][1][1] + __ldg(dec_b + t*3 + 1);
                        float a2 = dbuf[tid][0][2] + dbuf[tid][1][2] + __ldg(dec_b + t*3 + 2);
                        if (t == 2) {
                            float n = rsqrtf(a0*a0 + a1*a1 + a2*a2);
                            a0 *= n; a1 *= n; a2 *= n;
                        }
                        float* op = out + ((size_t)img * 3) * HWp + (y - 1) * Ww + (xx - 1);
                        op[0] = a0;
                        op[HWp] = a1;
                        op[2*HWp] = a2;
                    }
                }
            }
        }

        // module switch: re-stage weights + deferred chunk0 prefetch
        if (has_next && mod_sw) {
            __syncthreads();                 // everyone done with old weights
            stage_w(layer * Mm + g_sel[t2*Ll + layer]);
            stage_chunk(0, 0, nH, nL);
            cp_commit();
        }
        if (has_next) cur_mod_t = t2;
    }
}

extern "C" void kernel_launch(void* const* d_in, const int* in_sizes, int n_in,
                              void* d_out, int out_size) {
    const float* x      = (const float*)d_in[0];
    const float* alpha0 = (const float*)d_in[1];
    const float* alphas = (const float*)d_in[2];
    const float* g0     = (const float*)d_in[3];
    const float* gs     = (const float*)d_in[4];
    const float* enc_w  = (const float*)d_in[5];
    const float* enc_b  = (const float*)d_in[6];
    const float* dec_w  = (const float*)d_in[7];
    const float* dec_b  = (const float*)d_in[8];
    float* out = (float*)d_out;

    cudaFuncSetAttribute(conv_hmma, cudaFuncAttributeMaxDynamicSharedMemorySize, SMEM_TOT);

    prep_kernel<<<2363, 256>>>(x, alpha0, alphas, g0, gs, enc_w);

    conv_hmma<<<CTAS, 256, SMEM_TOT>>>(0, 1, 0, 0, enc_b, dec_w, dec_b, out);
    conv_hmma<<<CTAS, 256, SMEM_TOT>>>(1, 0, 0, 1, enc_b, dec_w, dec_b, out);
    conv_hmma<<<CTAS, 256, SMEM_TOT>>>(2, 0, 1, 0, enc_b, dec_w, dec_b, out);
    conv_hmma<<<CTAS, 256, SMEM_TOT>>>(3, 0, 0, 1, enc_b, dec_w, dec_b, out);
}

// round 7
// speedup vs baseline: 1.0029x; 1.0029x over previous
#include <cuda_runtime.h>
#include <cuda_bf16.h>
#include <cstdint>

#define Tt 3
#define Ll 4
#define Mm 3
#define Bb 8
#define Cc 64
#define Hh 128
#define Ww 128
#define HWp (Hh*Ww)
#define PW 130
#define PPX (PW*PW)              // 16900 padded pixels
#define FRONT 256
#define SLACK 384
#define PTOT (FRONT + PPX + SLACK)

#define TILE_M 256
#define HALO 131                 // PW + 1
#define STRIP_PX (TILE_M + 2*HALO)   // 518
#define CHUNK_B (STRIP_PX*32)        // 16576 bytes: 518 px x 16 ic x 2B
#define TILES 67                 // ceil(PPX/TILE_M)
#define CTAS 148
#define JOBS (Tt*Bb*TILES)       // 1608 jobs per layer

#define SW_OFF 0                 // weights: 9 taps x 2 halves x 8192 B = 147456
#define SA_OFF 147456            // A rings: [Ah0,Ah1,Al0,Al1] x 16576 = 66304
#define DBUF_OFF (SA_OFF + 4*CHUNK_B)  // 213760
#define SMEM_TOT (DBUF_OFF + 6144)     // 219904

// ---------------- device state ----------------
__device__ int g_sel[Tt*Ll];
// weights bf16: [mod 12][tap 9][half 2][oc 64][ic 64]
__device__ __align__(256) __nv_bfloat16 g_wB[(size_t)12*9*2*64*64];
// layer-0 input, padded NHWC bf16: [half][b][PTOT][64]
__device__ __align__(256) __nv_bfloat16 g_xp[2][(size_t)Bb*PTOT*Cc];
// ping-pong activations: [pp 2][half 2][t*b 24][PTOT][64]
__device__ __align__(256) __nv_bfloat16 g_act[2][2][(size_t)Tt*Bb*PTOT*Cc];

// ---------------- helpers ----------------
__device__ __forceinline__ uint32_t smem_u32(const void* p) {
    uint32_t a;
    asm("{ .reg .u64 t; cvta.to.shared.u64 t, %1; cvt.u32.u64 %0, t; }" : "=r"(a) : "l"(p));
    return a;
}
__device__ __forceinline__ void cp16(uint32_t sdst, const void* gsrc) {
    asm volatile("cp.async.cg.shared.global [%0], [%1], 16;" :: "r"(sdst), "l"(gsrc) : "memory");
}
__device__ __forceinline__ void cp_commit() { asm volatile("cp.async.commit_group;" ::: "memory"); }
template <int N>
__device__ __forceinline__ void cp_wait() {
    asm volatile("cp.async.wait_group %0;" :: "n"(N) : "memory");
}

__device__ __forceinline__ void ldmx4(uint32_t* r, uint32_t addr) {
    asm volatile("ldmatrix.sync.aligned.m8n8.x4.shared.b16 {%0,%1,%2,%3}, [%4];"
                 : "=r"(r[0]), "=r"(r[1]), "=r"(r[2]), "=r"(r[3]) : "r"(addr));
}
__device__ __forceinline__ void mma16816(float* c, const uint32_t* a, const uint32_t* b) {
    asm volatile("mma.sync.aligned.m16n8k16.row.col.f32.bf16.bf16.f32 "
                 "{%0,%1,%2,%3}, {%4,%5,%6,%7}, {%8,%9}, {%0,%1,%2,%3};"
                 : "+f"(c[0]), "+f"(c[1]), "+f"(c[2]), "+f"(c[3])
                 : "r"(a[0]), "r"(a[1]), "r"(a[2]), "r"(a[3]), "r"(b[0]), "r"(b[1]));
}

// ---------------- fused prep kernel ----------------------------------------
__global__ void __launch_bounds__(256) prep_kernel(
    const float* __restrict__ x, const float* __restrict__ alpha0,
    const float* __restrict__ alphas, const float* __restrict__ g0,
    const float* __restrict__ gs, const float* __restrict__ enc_w)
{
    const int bid = blockIdx.x;
    const int tid = threadIdx.x;

    if (bid < 128) {
        // ---- xprep: NCHW fp32 -> padded NHWC bf16 hi/lo, 4 px per thread ----
        int idx = bid * 256 + tid;            // [0, 32768)
        int b = idx >> 12;
        int pg = idx & 4095;
        int px0 = pg * 4;
        int y = px0 >> 7, x0 = px0 & 127;
        int p0 = (y + 1) * PW + (x0 + 1);
        const float* xs = x + ((size_t)b * Cc << 14) + px0;
        __nv_bfloat16* dh = g_xp[0] + ((size_t)b * PTOT + FRONT + p0) * Cc;
        __nv_bfloat16* dl = g_xp[1] + ((size_t)b * PTOT + FRONT + p0) * Cc;
        #pragma unroll
        for (int g = 0; g < 8; g++) {
            float4 v[8];
            #pragma unroll
            for (int j = 0; j < 8; j++)
                v[j] = *reinterpret_cast<const float4*>(xs + (size_t)(g*8 + j) * HWp);
            #pragma unroll
            for (int e = 0; e < 4; e++) {
                uint32_t hv[4], lv[4];
                #pragma unroll
                for (int q = 0; q < 4; q++) {
                    float f0 = (&v[q*2].x)[e];
                    float f1 = (&v[q*2+1].x)[e];
                    __nv_bfloat16 h0 = __float2bfloat16(f0);
                    __nv_bfloat16 h1 = __float2bfloat16(f1);
                    __nv_bfloat16 l0 = __float2bfloat16(f0 - __bfloat162float(h0));
                    __nv_bfloat16 l1 = __float2bfloat16(f1 - __bfloat162float(h1));
                    hv[q] = (uint32_t)__bfloat16_as_ushort(h1) << 16 | __bfloat16_as_ushort(h0);
                    lv[q] = (uint32_t)__bfloat16_as_ushort(l1) << 16 | __bfloat16_as_ushort(l0);
                }
                *reinterpret_cast<uint4*>(dh + (size_t)e * Cc + g*8) =
                    make_uint4(hv[0], hv[1], hv[2], hv[3]);
                *reinterpret_cast<uint4*>(dl + (size_t)e * Cc + g*8) =
                    make_uint4(lv[0], lv[1], lv[2], lv[3]);
            }
        }
    } else if (bid < 1856) {
        // ---- wprep ----
        int i = (bid - 128) * 256 + tid;       // [0, 442368)
        int ic  = i & 63;
        int oc  = (i >> 6) & 63;
        int tap = (i >> 12) % 9;
        int mod = i / 36864;
        float w = enc_w[(((size_t)(mod*Cc + oc))*Cc + ic)*9 + tap];
        __nv_bfloat16 hi = __float2bfloat16(w);
        __nv_bfloat16 lo = __float2bfloat16(w - __bfloat162float(hi));
        size_t base = (((size_t)mod*9 + tap)*2) * 4096 + oc*64 + ic;
        g_wB[base] = hi;
        g_wB[base + 4096] = lo;
    } else if (bid < 2362) {
        // ---- zero border pixels of all 112 padded planes ----
        int item = (bid - 1856) * 256 + tid;
        if (item >= 112 * 1156) return;
        int plane = item / 1156;
        int bi = item - plane * 1156;
        int px;
        if (bi < 256) px = bi;
        else {
            bi -= 256;
            if (bi < 130) px = FRONT + bi;
            else {
                bi -= 130;
                if (bi < 256) { int r = bi >> 1, c = bi & 1; px = FRONT + (r+1)*PW + c*129; }
                else {
                    bi -= 256;
                    if (bi < 130) px = FRONT + 129*PW + bi;
                    else px = FRONT + PPX + (bi - 130);
                }
            }
        }
        __nv_bfloat16* base;
        if (plane < 16) base = g_xp[plane >> 3] + (size_t)(plane & 7) * PTOT * Cc;
        else {
            int k = plane - 16; int arr = k / 24; int img = k % 24;
            base = g_act[arr >> 1][arr & 1] + (size_t)img * PTOT * Cc;
        }
        uint4 z = make_uint4(0, 0, 0, 0);
        uint4* d = (uint4*)(base + (size_t)px * Cc);
        #pragma unroll
        for (int q = 0; q < 8; q++) d[q] = z;
    } else {
        // ---- routing ----
        int t = tid;
        if (t >= Tt) return;
        int idx = 0;
        {
            float best = -1e30f; int bi2 = 0;
            #pragma unroll
            for (int m = 0; m < Mm; m++) {
                float v = alpha0[t*Mm + m] + g0[t*Mm + m];
                if (v > best) { best = v; bi2 = m; }
            }
            idx = bi2; g_sel[t*Ll + 0] = bi2;
        }
        for (int l = 1; l < Ll; l++) {
            const float* a = alphas + ((((size_t)(l-1)*Tt + t)*Mm + idx)*Mm);
            const float* g = gs     + ((((size_t)(l-1)*Tt + t)*Mm + idx)*Mm);
            float best = -1e30f; int bi2 = 0;
            #pragma unroll
            for (int m = 0; m < Mm; m++) {
                float v = a[m] + g[m];
                if (v > best) { best = v; bi2 = m; }
            }
            idx = bi2; g_sel[t*Ll + l] = bi2;
        }
    }
}

// ---------------- conv layer kernel (k-chunk streamed A, 1 barrier/k) -------
__global__ void __launch_bounds__(256) conv_hmma(
    int layer, int l0, int ps, int pd,
    const float* __restrict__ enc_b,
    const float* __restrict__ dec_w, const float* __restrict__ dec_b,
    float* __restrict__ out)
{
    extern __shared__ __align__(1024) char smem[];
    const uint32_t sb = smem_u32(smem);
    float (*dbuf)[2][3] = (float (*)[2][3])(smem + DBUF_OFF);
    const int tid = threadIdx.x;
    const int lane = tid & 31, wid = tid >> 5;
    const int wm = wid >> 1, wn = wid & 1;
    const int cta = blockIdx.x;

    const int nj = (cta < 128) ? 11 : 10;
    int j = (cta < 128) ? cta * 11 : 128 * 11 + (cta - 128) * 10;

    auto src_half = [&](int half, int img) -> const char* {
        const __nv_bfloat16* p;
        if (l0) p = g_xp[half] + ((size_t)(img & 7) * PTOT + FRONT) * Cc;
        else    p = g_act[ps][half] + ((size_t)img * PTOT + FRONT) * Cc;
        return (const char*)p;
    };
    auto stage_chunk = [&](int kc, int slot, const char* sH, const char* sL) {
        uint32_t dA = sb + SA_OFF + slot * CHUNK_B;
        uint32_t dB = dA + 2 * CHUNK_B;
        int ko = kc * 32;
        for (int i = tid; i < 2 * STRIP_PX; i += 256) {
            int px = i >> 1;
            int c = (i & 1) << 4;
            uint32_t sw = px * 32 + (uint32_t)(c ^ (((px >> 2) & 1) << 4));
            size_t go = (size_t)px * 128 + ko + c;
            cp16(dA + sw, sH + go);
            cp16(dB + sw, sL + go);
        }
    };
    auto stage_w = [&](int mod) {
        const char* wsrc = (const char*)g_wB + (size_t)mod * 147456;
        for (int g = tid; g < 9216; g += 256) {
            int tile = g >> 9;
            int o = (g & 511) * 16;
            int sw = o ^ ((o >> 3) & 0x70);
            cp16(sb + SW_OFF + tile * 8192 + sw, wsrc + tile * 8192 + o);
        }
    };

    // ---- fragment index precompute ----
    const int arow = lane & 15;
    const int acol = (lane >> 4) << 4;
    const int ocl = (lane & 7) + ((lane >> 4) << 3);
    const int bkhalf = ((lane >> 3) & 1) * 16;
    int obase[2], oxor[2];
    #pragma unroll
    for (int pr = 0; pr < 2; pr++) {
        int oc = wn * 32 + pr * 16 + ocl;
        obase[pr] = oc * 128;
        oxor[pr] = (oc & 7) << 4;
    }

    // prologue: weights + chunk0 of first tile
    {
        const int img0 = j / TILES;
        const int tile0 = j - img0 * TILES;
        const int t0 = img0 >> 3;
        stage_w(layer * Mm + g_sel[t0*Ll + layer]);
        stage_chunk(0, 0,
                    src_half(0, img0) + (size_t)(tile0*TILE_M - HALO) * 128,
                    src_half(1, img0) + (size_t)(tile0*TILE_M - HALO) * 128);
        cp_commit();
    }
    int cur_mod_t = (j / TILES) >> 3;

    for (int jj = 0; jj < nj; jj++, j++) {
        const int img = j / TILES;
        const int tile = j - img * TILES;
        const int t = img >> 3;
        const int tb = tile * TILE_M;
        const int mod = layer * Mm + g_sel[t*Ll + layer];
        const char* sH = src_half(0, img) + (size_t)(tb - HALO) * 128;
        const char* sL = src_half(1, img) + (size_t)(tb - HALO) * 128;

        bool has_next = (jj + 1 < nj);
        int t2 = 0;
        bool mod_sw = false;
        const char* nH = nullptr; const char* nL = nullptr;
        if (has_next) {
            int j2 = j + 1;
            int img2 = j2 / TILES;
            int tb2 = (j2 - img2 * TILES) * TILE_M;
            t2 = img2 >> 3;
            mod_sw = (t2 != cur_mod_t) &&
                     (g_sel[t2*Ll + layer] != g_sel[cur_mod_t*Ll + layer]);
            nH = src_half(0, img2) + (size_t)(tb2 - HALO) * 128;
            nL = src_half(1, img2) + (size_t)(tb2 - HALO) * 128;
        }

        float acc[4][4][4];
        #pragma unroll
        for (int mt = 0; mt < 4; mt++)
            #pragma unroll
            for (int nt = 0; nt < 4; nt++)
                #pragma unroll
                for (int r = 0; r < 4; r++) acc[mt][nt][r] = 0.f;

        for (int k = 0; k < 4; k++) {
            cp_wait<0>();
            __syncthreads();   // chunk k visible to all; slot (k+1)&1 free

            if (k < 3) { stage_chunk(k + 1, (k + 1) & 1, sH, sL); cp_commit(); }
            else if (has_next && !mod_sw) { stage_chunk(0, 0, nH, nL); cp_commit(); }

            const uint32_t aHb = sb + SA_OFF + (k & 1) * CHUNK_B;
            const int kb = k * 32 + bkhalf;

            #pragma unroll
            for (int tap = 0; tap < 9; tap++) {
                const int dy = tap / 3 - 1, dx = tap % 3 - 1;
                const int pxoff = HALO + dy * PW + dx;
                const uint32_t bbh = sb + SW_OFF + tap * 16384;

                uint32_t bh[4][2], bl[4][2];
                #pragma unroll
                for (int pr = 0; pr < 2; pr++) {
                    uint32_t off = obase[pr] + (uint32_t)(kb ^ oxor[pr]);
                    uint32_t r[4];
                    ldmx4(r, bbh + off);
                    bh[pr*2][0] = r[0]; bh[pr*2][1] = r[1];
                    bh[pr*2+1][0] = r[2]; bh[pr*2+1][1] = r[3];
                    ldmx4(r, bbh + 8192 + off);
                    bl[pr*2][0] = r[0]; bl[pr*2][1] = r[1];
                    bl[pr*2+1][0] = r[2]; bl[pr*2+1][1] = r[3];
                }
                uint32_t aH[4][4], aL[4][4];
                #pragma unroll
                for (int mt = 0; mt < 4; mt++) {
                    int px = wm * 64 + mt * 16 + arow + pxoff;
                    uint32_t sw = px * 32 + (uint32_t)(acol ^ (((px >> 2) & 1) << 4));
                    ldmx4(aH[mt], aHb + sw);
                    ldmx4(aL[mt], aHb + 2 * CHUNK_B + sw);
                }
                // term-major: independent accumulators between reuses
                #pragma unroll
                for (int mt = 0; mt < 4; mt++)
                    #pragma unroll
                    for (int nt = 0; nt < 4; nt++)
                        mma16816(acc[mt][nt], aH[mt], bh[nt]);
                #pragma unroll
                for (int mt = 0; mt < 4; mt++)
                    #pragma unroll
                    for (int nt = 0; nt < 4; nt++)
                        mma16816(acc[mt][nt], aH[mt], bl[nt]);
                #pragma unroll
                for (int mt = 0; mt < 4; mt++)
                    #pragma unroll
                    for (int nt = 0; nt < 4; nt++)
                        mma16816(acc[mt][nt], aL[mt], bh[nt]);
            }
        }

        // module switch: re-stage weights + deferred chunk0 prefetch
        if (has_next && mod_sw) {
            __syncthreads();               // all warps done with old weights
            stage_w(layer * Mm + g_sel[t2*Ll + layer]);
            stage_chunk(0, 0, nH, nL);
            cp_commit();
        }

        const int g = lane >> 2, c2 = (lane & 3) * 2;
        const float* bb = enc_b + mod * 64;

        if (layer != 3) {
            __nv_bfloat16* dst_h = g_act[pd][0] + ((size_t)img * PTOT + FRONT) * Cc;
            __nv_bfloat16* dst_l = g_act[pd][1] + ((size_t)img * PTOT + FRONT) * Cc;
            #pragma unroll
            for (int mt = 0; mt < 4; mt++) {
                #pragma unroll
                for (int r = 0; r < 2; r++) {
                    int row = wm * 64 + mt * 16 + g + r * 8;
                    int p = tb + row;
                    if (p < PPX) {
                        int y = p / PW, xx = p - y * PW;
                        if (y >= 1 && y <= Hh && xx >= 1 && xx <= Ww) {
                            size_t base = (size_t)p * Cc;
                            #pragma unroll
                            for (int nt = 0; nt < 4; nt++) {
                                int oc = wn * 32 + nt * 8 + c2;
                                float f0 = fmaxf(acc[mt][nt][r*2+0] + __ldg(bb + oc),     0.f);
                                float f1 = fmaxf(acc[mt][nt][r*2+1] + __ldg(bb + oc + 1), 0.f);
                                __nv_bfloat16 h0 = __float2bfloat16(f0);
                                __nv_bfloat16 h1 = __float2bfloat16(f1);
                                __nv_bfloat16 l0 = __float2bfloat16(f0 - __bfloat162float(h0));
                                __nv_bfloat16 l1 = __float2bfloat16(f1 - __bfloat162float(h1));
                                uint32_t hw = (uint32_t)__bfloat16_as_ushort(h1) << 16 | __bfloat16_as_ushort(h0);
                                uint32_t lw = (uint32_t)__bfloat16_as_ushort(l1) << 16 | __bfloat16_as_ushort(l0);
                                *(uint32_t*)(dst_h + base + oc) = hw;
                                *(uint32_t*)(dst_l + base + oc) = lw;
                            }
                        }
                    }
                }
            }
        } else {
            // fused decoder
            float wd[3][8];
            #pragma unroll
            for (int kk = 0; kk < 3; kk++)
                #pragma unroll
                for (int q = 0; q < 8; q++) {
                    int oc = wn * 32 + (q >> 1) * 8 + c2 + (q & 1);
                    wd[kk][q] = __ldg(dec_w + ((size_t)t * 3 + kk) * 64 + oc);
                }
            #pragma unroll
            for (int mt = 0; mt < 4; mt++) {
                #pragma unroll
                for (int r = 0; r < 2; r++) {
                    float p0 = 0.f, p1 = 0.f, p2 = 0.f;
                    #pragma unroll
                    for (int nt = 0; nt < 4; nt++) {
                        int oc = wn * 32 + nt * 8 + c2;
                        float f0 = fmaxf(acc[mt][nt][r*2+0] + __ldg(bb + oc),     0.f);
                        float f1 = fmaxf(acc[mt][nt][r*2+1] + __ldg(bb + oc + 1), 0.f);
                        p0 = fmaf(f0, wd[0][nt*2+0], fmaf(f1, wd[0][nt*2+1], p0));
                        p1 = fmaf(f0, wd[1][nt*2+0], fmaf(f1, wd[1][nt*2+1], p1));
                        p2 = fmaf(f0, wd[2][nt*2+0], fmaf(f1, wd[2][nt*2+1], p2));
                    }
                    #pragma unroll
                    for (int off = 1; off < 4; off <<= 1) {
                        p0 += __shfl_xor_sync(0xffffffffu, p0, off);
                        p1 += __shfl_xor_sync(0xffffffffu, p1, off);
                        p2 += __shfl_xor_sync(0xffffffffu, p2, off);
                    }
                    if ((lane & 3) == 0) {
                        int pix = wm * 64 + mt * 16 + r * 8 + g;
                        dbuf[pix][wn][0] = p0;
                        dbuf[pix][wn][1] = p1;
                        dbuf[pix][wn][2] = p2;
                    }
                }
            }
            __syncthreads();
            {
                int p = tb + tid;
                if (p < PPX) {
                    int y = p / PW, xx = p - y * PW;
                    if (y >= 1 && y <= Hh && xx >= 1 && xx <= Ww) {
                        float a0 = dbuf[tid][0][0] + dbuf[tid][1][0] + __ldg(dec_b + t*3 + 0);
                        float a1 = dbuf[tid][0][1] + dbuf[tid][1][1] + __ldg(dec_b + t*3 + 1);
                        float a2 = dbuf[tid][0][2] + dbuf[tid][1][2] + __ldg(dec_b + t*3 + 2);
                        if (t == 2) {
                            float n = rsqrtf(a0*a0 + a1*a1 + a2*a2);
                            a0 *= n; a1 *= n; a2 *= n;
                        }
                        float* op = out + ((size_t)img * 3) * HWp + (y - 1) * Ww + (xx - 1);
                        op[0] = a0;
                        op[HWp] = a1;
                        op[2*HWp] = a2;
                    }
                }
            }
        }

        if (has_next) cur_mod_t = t2;
    }
}

extern "C" void kernel_launch(void* const* d_in, const int* in_sizes, int n_in,
                              void* d_out, int out_size) {
    const float* x      = (const float*)d_in[0];
    const float* alpha0 = (const float*)d_in[1];
    const float* alphas = (const float*)d_in[2];
    const float* g0     = (const float*)d_in[3];
    const float* gs     = (const float*)d_in[4];
    const float* enc_w  = (const float*)d_in[5];
    const float* enc_b  = (const float*)d_in[6];
    const float* dec_w  = (const float*)d_in[7];
    const float* dec_b  = (const float*)d_in[8];
    float* out = (float*)d_out;

    cudaFuncSetAttribute(conv_hmma, cudaFuncAttributeMaxDynamicSharedMemorySize, SMEM_TOT);

    prep_kernel<<<2363, 256>>>(x, alpha0, alphas, g0, gs, enc_w);

    conv_hmma<<<CTAS, 256, SMEM_TOT>>>(0, 1, 0, 0, enc_b, dec_w, dec_b, out);
    conv_hmma<<<CTAS, 256, SMEM_TOT>>>(1, 0, 0, 1, enc_b, dec_w, dec_b, out);
    conv_hmma<<<CTAS, 256, SMEM_TOT>>>(2, 0, 1, 0, enc_b, dec_w, dec_b, out);
    conv_hmma<<<CTAS, 256, SMEM_TOT>>>(3, 0, 0, 1, enc_b, dec_w, dec_b, out);
}

// round 8
// speedup vs baseline: 1.0396x; 1.0366x over previous
#include <cuda_runtime.h>
#include <cuda_bf16.h>
#include <cstdint>

#define Tt 3
#define Ll 4
#define Mm 3
#define Bb 8
#define Cc 64
#define Hh 128
#define Ww 128
#define HWp (Hh*Ww)
#define PW 130
#define PPX (PW*PW)              // 16900 padded pixels
#define FRONT 256
#define SLACK 384
#define PTOT (FRONT + PPX + SLACK)

#define TILE_M 256
#define HALO 131                 // PW + 1
#define STRIP_PX (TILE_M + 2*HALO)   // 518
#define STRIP_B (STRIP_PX*128)       // 66304 bytes per half
#define TILES 67                 // ceil(PPX/TILE_M)
#define CTAS 148
#define JOBS (Tt*Bb*TILES)       // 1608 jobs per layer

#define SW_OFF 0                 // weights: 9 taps x 2 halves x 8192 B = 147456
#define SA_OFF 147456            // A buffer: 66304 B (Ah, then Al overwrites)
#define DBUF_OFF (SA_OFF + STRIP_B)  // 213760
#define SMEM_TOT (DBUF_OFF + 6144)   // 219904

// ---------------- device state ----------------
__device__ int g_sel[Tt*Ll];
// weights bf16: [mod 12][tap 9][half 2][oc 64][ic 64]
__device__ __align__(256) __nv_bfloat16 g_wB[(size_t)12*9*2*64*64];
// layer-0 input, padded NHWC bf16: [half][b][PTOT][64]
__device__ __align__(256) __nv_bfloat16 g_xp[2][(size_t)Bb*PTOT*Cc];
// ping-pong activations: [pp 2][half 2][t*b 24][PTOT][64]
__device__ __align__(256) __nv_bfloat16 g_act[2][2][(size_t)Tt*Bb*PTOT*Cc];

// ---------------- helpers ----------------
__device__ __forceinline__ uint32_t smem_u32(const void* p) {
    uint32_t a;
    asm("{ .reg .u64 t; cvta.to.shared.u64 t, %1; cvt.u32.u64 %0, t; }" : "=r"(a) : "l"(p));
    return a;
}
__device__ __forceinline__ void cp16(uint32_t sdst, const void* gsrc) {
    asm volatile("cp.async.cg.shared.global [%0], [%1], 16;" :: "r"(sdst), "l"(gsrc) : "memory");
}
__device__ __forceinline__ void cp_commit() { asm volatile("cp.async.commit_group;" ::: "memory"); }
template <int N>
__device__ __forceinline__ void cp_wait() {
    asm volatile("cp.async.wait_group %0;" :: "n"(N) : "memory");
}

__device__ __forceinline__ void ldmx4(uint32_t* r, uint32_t addr) {
    asm volatile("ldmatrix.sync.aligned.m8n8.x4.shared.b16 {%0,%1,%2,%3}, [%4];"
                 : "=r"(r[0]), "=r"(r[1]), "=r"(r[2]), "=r"(r[3]) : "r"(addr));
}
__device__ __forceinline__ void mma16816(float* c, const uint32_t* a, const uint32_t* b) {
    asm volatile("mma.sync.aligned.m16n8k16.row.col.f32.bf16.bf16.f32 "
                 "{%0,%1,%2,%3}, {%4,%5,%6,%7}, {%8,%9}, {%0,%1,%2,%3};"
                 : "+f"(c[0]), "+f"(c[1]), "+f"(c[2]), "+f"(c[3])
                 : "r"(a[0]), "r"(a[1]), "r"(a[2]), "r"(a[3]), "r"(b[0]), "r"(b[1]));
}
// packed hi/lo bf16 split: f0,f1 -> hw (bf16x2), lw (bf16x2 of residuals)
__device__ __forceinline__ void split2(float f0, float f1, uint32_t& hw, uint32_t& lw) {
    asm("cvt.rn.bf16x2.f32 %0, %1, %2;" : "=r"(hw) : "f"(f1), "f"(f0));
    float f0h = __uint_as_float(hw << 16);
    float f1h = __uint_as_float(hw & 0xffff0000u);
    float l0 = f0 - f0h;
    float l1 = f1 - f1h;
    asm("cvt.rn.bf16x2.f32 %0, %1, %2;" : "=r"(lw) : "f"(l1), "f"(l0));
}

// ---------------- fused prep kernel ----------------------------------------
__global__ void __launch_bounds__(256) prep_kernel(
    const float* __restrict__ x, const float* __restrict__ alpha0,
    const float* __restrict__ alphas, const float* __restrict__ g0,
    const float* __restrict__ gs, const float* __restrict__ enc_w)
{
    const int bid = blockIdx.x;
    const int tid = threadIdx.x;

    if (bid < 128) {
        // ---- xprep: NCHW fp32 -> padded NHWC bf16 hi/lo, 4 px per thread ----
        int idx = bid * 256 + tid;            // [0, 32768)
        int b = idx >> 12;
        int pg = idx & 4095;
        int px0 = pg * 4;
        int y = px0 >> 7, x0 = px0 & 127;
        int p0 = (y + 1) * PW + (x0 + 1);
        const float* xs = x + ((size_t)b * Cc << 14) + px0;
        __nv_bfloat16* dh = g_xp[0] + ((size_t)b * PTOT + FRONT + p0) * Cc;
        __nv_bfloat16* dl = g_xp[1] + ((size_t)b * PTOT + FRONT + p0) * Cc;
        #pragma unroll
        for (int g = 0; g < 8; g++) {
            float4 v[8];
            #pragma unroll
            for (int j = 0; j < 8; j++)
                v[j] = *reinterpret_cast<const float4*>(xs + (size_t)(g*8 + j) * HWp);
            #pragma unroll
            for (int e = 0; e < 4; e++) {
                uint32_t hv[4], lv[4];
                #pragma unroll
                for (int q = 0; q < 4; q++) {
                    float f0 = (&v[q*2].x)[e];
                    float f1 = (&v[q*2+1].x)[e];
                    split2(f0, f1, hv[q], lv[q]);
                }
                *reinterpret_cast<uint4*>(dh + (size_t)e * Cc + g*8) =
                    make_uint4(hv[0], hv[1], hv[2], hv[3]);
                *reinterpret_cast<uint4*>(dl + (size_t)e * Cc + g*8) =
                    make_uint4(lv[0], lv[1], lv[2], lv[3]);
            }
        }
    } else if (bid < 1856) {
        // ---- wprep ----
        int i = (bid - 128) * 256 + tid;       // [0, 442368)
        int ic  = i & 63;
        int oc  = (i >> 6) & 63;
        int tap = (i >> 12) % 9;
        int mod = i / 36864;
        float w = enc_w[(((size_t)(mod*Cc + oc))*Cc + ic)*9 + tap];
        __nv_bfloat16 hi = __float2bfloat16(w);
        __nv_bfloat16 lo = __float2bfloat16(w - __bfloat162float(hi));
        size_t base = (((size_t)mod*9 + tap)*2) * 4096 + oc*64 + ic;
        g_wB[base] = hi;
        g_wB[base + 4096] = lo;
    } else if (bid < 2362) {
        // ---- zero border pixels of all 112 padded planes ----
        int item = (bid - 1856) * 256 + tid;
        if (item >= 112 * 1156) return;
        int plane = item / 1156;
        int bi = item - plane * 1156;
        int px;
        if (bi < 256) px = bi;
        else {
            bi -= 256;
            if (bi < 130) px = FRONT + bi;
            else {
                bi -= 130;
                if (bi < 256) { int r = bi >> 1, c = bi & 1; px = FRONT + (r+1)*PW + c*129; }
                else {
                    bi -= 256;
                    if (bi < 130) px = FRONT + 129*PW + bi;
                    else px = FRONT + PPX + (bi - 130);
                }
            }
        }
        __nv_bfloat16* base;
        if (plane < 16) base = g_xp[plane >> 3] + (size_t)(plane & 7) * PTOT * Cc;
        else {
            int k = plane - 16; int arr = k / 24; int img = k % 24;
            base = g_act[arr >> 1][arr & 1] + (size_t)img * PTOT * Cc;
        }
        uint4 z = make_uint4(0, 0, 0, 0);
        uint4* d = (uint4*)(base + (size_t)px * Cc);
        #pragma unroll
        for (int q = 0; q < 8; q++) d[q] = z;
    } else {
        // ---- routing ----
        int t = tid;
        if (t >= Tt) return;
        int idx = 0;
        {
            float best = -1e30f; int bi2 = 0;
            #pragma unroll
            for (int m = 0; m < Mm; m++) {
                float v = alpha0[t*Mm + m] + g0[t*Mm + m];
                if (v > best) { best = v; bi2 = m; }
            }
            idx = bi2; g_sel[t*Ll + 0] = bi2;
        }
        for (int l = 1; l < Ll; l++) {
            const float* a = alphas + ((((size_t)(l-1)*Tt + t)*Mm + idx)*Mm);
            const float* g = gs     + ((((size_t)(l-1)*Tt + t)*Mm + idx)*Mm);
            float best = -1e30f; int bi2 = 0;
            #pragma unroll
            for (int m = 0; m < Mm; m++) {
                float v = a[m] + g[m];
                if (v > best) { best = v; bi2 = m; }
            }
            idx = bi2; g_sel[t*Ll + l] = bi2;
        }
    }
}

// ---------------- conv pass: taps x k-range of m16n8k16, term-major --------
// dual: acc += Ah*Bh (+ Ah*Bl). !dual: acc += Al*Bh.
__device__ __forceinline__ void conv_pass(float (*acc)[4][4], uint32_t sb,
                                          int lane, int wm, int wn,
                                          int klo, int khi, bool dual) {
    const int arow = lane & 15;
    const int akhalf = (lane >> 4) * 16;
    const int ocl = (lane & 7) + ((lane >> 4) << 3);
    const int bkhalf = ((lane >> 3) & 1) * 16;

    for (int tap = 0; tap < 9; tap++) {
        const int dy = tap / 3 - 1, dx = tap % 3 - 1;
        const int pxoff = HALO + dy * PW + dx;
        const uint32_t bbh = sb + SW_OFF + tap * 16384;

        int abase[4], axor[4];
        #pragma unroll
        for (int mt = 0; mt < 4; mt++) {
            int px = wm * 64 + mt * 16 + arow + pxoff;
            abase[mt] = px * 128;
            axor[mt] = (px & 7) << 4;
        }
        int obase[2], oxor[2];
        #pragma unroll
        for (int pr = 0; pr < 2; pr++) {
            int oc = wn * 32 + pr * 16 + ocl;
            obase[pr] = oc * 128;
            oxor[pr] = (oc & 7) << 4;
        }

        for (int k = klo; k < khi; k++) {
            uint32_t aF[4][4];
            #pragma unroll
            for (int mt = 0; mt < 4; mt++) {
                uint32_t addr = sb + SA_OFF + abase[mt]
                              + (uint32_t)((k * 32 + akhalf) ^ axor[mt]);
                ldmx4(aF[mt], addr);
            }
            uint32_t bh[4][2];
            #pragma unroll
            for (int pr = 0; pr < 2; pr++) {
                uint32_t off = obase[pr] + (uint32_t)((k * 32 + bkhalf) ^ oxor[pr]);
                uint32_t r[4];
                ldmx4(r, bbh + off);
                bh[pr*2][0] = r[0]; bh[pr*2][1] = r[1];
                bh[pr*2+1][0] = r[2]; bh[pr*2+1][1] = r[3];
            }
            #pragma unroll
            for (int mt = 0; mt < 4; mt++)
                #pragma unroll
                for (int nt = 0; nt < 4; nt++)
                    mma16816(acc[mt][nt], aF[mt], bh[nt]);
            if (dual) {
                uint32_t bl[4][2];
                #pragma unroll
                for (int pr = 0; pr < 2; pr++) {
                    uint32_t off = obase[pr] + (uint32_t)((k * 32 + bkhalf) ^ oxor[pr]);
                    uint32_t r[4];
                    ldmx4(r, bbh + 8192 + off);
                    bl[pr*2][0] = r[0]; bl[pr*2][1] = r[1];
                    bl[pr*2+1][0] = r[2]; bl[pr*2+1][1] = r[3];
                }
                #pragma unroll
                for (int mt = 0; mt < 4; mt++)
                    #pragma unroll
                    for (int nt = 0; nt < 4; nt++)
                        mma16816(acc[mt][nt], aF[mt], bl[nt]);
            }
        }
    }
}

// ---------------- conv layer kernel ----------------------------------------
__global__ void __launch_bounds__(256) conv_hmma(
    int layer, int l0, int ps, int pd,
    const float* __restrict__ enc_b,
    const float* __restrict__ dec_w, const float* __restrict__ dec_b,
    float* __restrict__ out)
{
    extern __shared__ __align__(1024) char smem[];
    const uint32_t sb = smem_u32(smem);
    float (*dbuf)[2][3] = (float (*)[2][3])(smem + DBUF_OFF);
    const int tid = threadIdx.x;
    const int lane = tid & 31, wid = tid >> 5;
    const int wm = wid >> 1, wn = wid & 1;
    const int cta = blockIdx.x;

    const int nj = (cta < 128) ? 11 : 10;
    int j = (cta < 128) ? cta * 11 : 128 * 11 + (cta - 128) * 10;

    auto src_half = [&](int half, int img) -> const char* {
        const __nv_bfloat16* p;
        if (l0) p = g_xp[half] + ((size_t)(img & 7) * PTOT + FRONT) * Cc;
        else    p = g_act[ps][half] + ((size_t)img * PTOT + FRONT) * Cc;
        return (const char*)p;
    };
    // stage full 64-ic strip (66304 B)
    auto stage = [&](const char* src, int tb) {
        const char* g = src + (size_t)(tb - HALO) * 128;
        for (int i = tid; i < STRIP_PX * 8; i += 256) {
            int px = i >> 3;
            int c = (i & 7) << 4;
            uint32_t sw = (uint32_t)(px * 128 + (c ^ ((px & 7) << 4)));
            cp16(sb + SA_OFF + sw, g + (size_t)px * 128 + c);
        }
    };
    // stage one 32-ic half of the strip (33152 B), half = 0 or 1
    auto stage_half = [&](const char* src, int tb, int half) {
        const char* g = src + (size_t)(tb - HALO) * 128;
        const int h64 = half * 64;
        for (int i = tid; i < STRIP_PX * 4; i += 256) {
            int px = i >> 2;
            int c = h64 + ((i & 3) << 4);
            uint32_t sw = (uint32_t)(px * 128 + (c ^ ((px & 7) << 4)));
            cp16(sb + SA_OFF + sw, g + (size_t)px * 128 + c);
        }
    };
    auto stage_w = [&](int mod) {
        const char* wsrc = (const char*)g_wB + (size_t)mod * 147456;
        for (int g = tid; g < 9216; g += 256) {
            int tile = g >> 9;
            int o = (g & 511) * 16;
            int sw = o ^ ((o >> 3) & 0x70);
            cp16(sb + SW_OFF + tile * 8192 + sw, wsrc + tile * 8192 + o);
        }
    };

    // prologue: weights + Ah of first tile
    {
        const int img0 = j / TILES;
        const int tile0 = j - img0 * TILES;
        const int t0 = img0 >> 3;
        stage_w(layer * Mm + g_sel[t0*Ll + layer]);
        stage(src_half(0, img0), tile0 * TILE_M);
        cp_commit();
    }
    int cur_mod_t = (j / TILES) >> 3;

    for (int jj = 0; jj < nj; jj++, j++) {
        const int img = j / TILES;
        const int tile = j - img * TILES;
        const int t = img >> 3;
        const int tb = tile * TILE_M;
        const int mod = layer * Mm + g_sel[t*Ll + layer];
        const char* sL = src_half(1, img);

        bool has_next = (jj + 1 < nj);
        int t2 = 0;
        bool mod_sw = false;
        const char* nH = nullptr;
        int ntb = 0;
        if (has_next) {
            int j2 = j + 1;
            int img2 = j2 / TILES;
            ntb = (j2 - img2 * TILES) * TILE_M;
            t2 = img2 >> 3;
            mod_sw = (t2 != cur_mod_t) &&
                     (g_sel[t2*Ll + layer] != g_sel[cur_mod_t*Ll + layer]);
            nH = src_half(0, img2);
        }

        float acc[4][4][4];
        #pragma unroll
        for (int mt = 0; mt < 4; mt++)
            #pragma unroll
            for (int nt = 0; nt < 4; nt++)
                #pragma unroll
                for (int r = 0; r < 4; r++) acc[mt][nt][r] = 0.f;

        cp_wait<0>();
        __syncthreads();                    // Ah + weights ready

        conv_pass(acc, sb, lane, wm, wn, 0, 4, true);   // Ah*Bh + Ah*Bl (term-major)

        __syncthreads();                    // all warps done reading Ah
        stage_half(sL, tb, 0); cp_commit(); // Al ic 0..31  (group g1)
        stage_half(sL, tb, 1); cp_commit(); // Al ic 32..63 (group g2)

        cp_wait<1>();                       // g1 landed
        __syncthreads();
        conv_pass(acc, sb, lane, wm, wn, 0, 2, false);  // Al*Bh, k 0..1

        cp_wait<0>();                       // g2 landed
        __syncthreads();
        conv_pass(acc, sb, lane, wm, wn, 2, 4, false);  // Al*Bh, k 2..3

        __syncthreads();                    // all warps done reading Al
        if (has_next) {
            stage(nH, ntb);                 // next Ah — hidden under epilogue+entry
            cp_commit();
        }

        const int g = lane >> 2, c2 = (lane & 3) * 2;
        const float* bb = enc_b + mod * 64;

        if (layer != 3) {
            __nv_bfloat16* dst_h = g_act[pd][0] + ((size_t)img * PTOT + FRONT) * Cc;
            __nv_bfloat16* dst_l = g_act[pd][1] + ((size_t)img * PTOT + FRONT) * Cc;
            #pragma unroll
            for (int mt = 0; mt < 4; mt++) {
                #pragma unroll
                for (int r = 0; r < 2; r++) {
                    int row = wm * 64 + mt * 16 + g + r * 8;
                    int p = tb + row;
                    if (p < PPX) {
                        int y = p / PW, xx = p - y * PW;
                        if (y >= 1 && y <= Hh && xx >= 1 && xx <= Ww) {
                            size_t base = (size_t)p * Cc;
                            #pragma unroll
                            for (int nt = 0; nt < 4; nt++) {
                                int oc = wn * 32 + nt * 8 + c2;
                                float f0 = fmaxf(acc[mt][nt][r*2+0] + __ldg(bb + oc),     0.f);
                                float f1 = fmaxf(acc[mt][nt][r*2+1] + __ldg(bb + oc + 1), 0.f);
                                uint32_t hw, lw;
                                split2(f0, f1, hw, lw);
                                *(uint32_t*)(dst_h + base + oc) = hw;
                                *(uint32_t*)(dst_l + base + oc) = lw;
                            }
                        }
                    }
                }
            }
        } else {
            // fused decoder
            float wd[3][8];
            #pragma unroll
            for (int kk = 0; kk < 3; kk++)
                #pragma unroll
                for (int q = 0; q < 8; q++) {
                    int oc = wn * 32 + (q >> 1) * 8 + c2 + (q & 1);
                    wd[kk][q] = __ldg(dec_w + ((size_t)t * 3 + kk) * 64 + oc);
                }
            #pragma unroll
            for (int mt = 0; mt < 4; mt++) {
                #pragma unroll
                for (int r = 0; r < 2; r++) {
                    float p0 = 0.f, p1 = 0.f, p2 = 0.f;
                    #pragma unroll
                    for (int nt = 0; nt < 4; nt++) {
                        int oc = wn * 32 + nt * 8 + c2;
                        float f0 = fmaxf(acc[mt][nt][r*2+0] + __ldg(bb + oc),     0.f);
                        float f1 = fmaxf(acc[mt][nt][r*2+1] + __ldg(bb + oc + 1), 0.f);
                        p0 = fmaf(f0, wd[0][nt*2+0], fmaf(f1, wd[0][nt*2+1], p0));
                        p1 = fmaf(f0, wd[1][nt*2+0], fmaf(f1, wd[1][nt*2+1], p1));
                        p2 = fmaf(f0, wd[2][nt*2+0], fmaf(f1, wd[2][nt*2+1], p2));
                    }
                    #pragma unroll
                    for (int off = 1; off < 4; off <<= 1) {
                        p0 += __shfl_xor_sync(0xffffffffu, p0, off);
                        p1 += __shfl_xor_sync(0xffffffffu, p1, off);
                        p2 += __shfl_xor_sync(0xffffffffu, p2, off);
                    }
                    if ((lane & 3) == 0) {
                        int pix = wm * 64 + mt * 16 + r * 8 + g;
                        dbuf[pix][wn][0] = p0;
                        dbuf[pix][wn][1] = p1;
                        dbuf[pix][wn][2] = p2;
                    }
                }
            }
            __syncthreads();
            {
                int p = tb + tid;
                if (p < PPX) {
                    int y = p / PW, xx = p - y * PW;
                    if (y >= 1 && y <= Hh && xx >= 1 && xx <= Ww) {
                        float a0 = dbuf[tid][0][0] + dbuf[tid][1][0] + __ldg(dec_b + t*3 + 0);
                        float a1 = dbuf[tid][0][1] + dbuf[tid][1][1] + __ldg(dec_b + t*3 + 1);
                        float a2 = dbuf[tid][0][2] + dbuf[tid][1][2] + __ldg(dec_b + t*3 + 2);
                        if (t == 2) {
                            float n = rsqrtf(a0*a0 + a1*a1 + a2*a2);
                            a0 *= n; a1 *= n; a2 *= n;
                        }
                        float* op = out + ((size_t)img * 3) * HWp + (y - 1) * Ww + (xx - 1);
                        op[0] = a0;
                        op[HWp] = a1;
                        op[2*HWp] = a2;
                    }
                }
            }
        }

        // module switch: re-stage weights after all warps done with old ones
        if (has_next && mod_sw) {
            __syncthreads();
            stage_w(layer * Mm + g_sel[t2*Ll + layer]);
            cp_commit();
        }
        if (has_next) cur_mod_t = t2;
    }
}

extern "C" void kernel_launch(void* const* d_in, const int* in_sizes, int n_in,
                              void* d_out, int out_size) {
    const float* x      = (const float*)d_in[0];
    const float* alpha0 = (const float*)d_in[1];
    const float* alphas = (const float*)d_in[2];
    const float* g0     = (const float*)d_in[3];
    const float* gs     = (const float*)d_in[4];
    const float* enc_w  = (const float*)d_in[5];
    const float* enc_b  = (const float*)d_in[6];
    const float* dec_w  = (const float*)d_in[7];
    const float* dec_b  = (const float*)d_in[8];
    float* out = (float*)d_out;

    cudaFuncSetAttribute(conv_hmma, cudaFuncAttributeMaxDynamicSharedMemorySize, SMEM_TOT);

    prep_kernel<<<2363, 256>>>(x, alpha0, alphas, g0, gs, enc_w);

    conv_hmma<<<CTAS, 256, SMEM_TOT>>>(0, 1, 0, 0, enc_b, dec_w, dec_b, out);
    conv_hmma<<<CTAS, 256, SMEM_TOT>>>(1, 0, 0, 1, enc_b, dec_w, dec_b, out);
    conv_hmma<<<CTAS, 256, SMEM_TOT>>>(2, 0, 1, 0, enc_b, dec_w, dec_b, out);
    conv_hmma<<<CTAS, 256, SMEM_TOT>>>(3, 0, 0, 1, enc_b, dec_w, dec_b, out);
}

// round 9
// speedup vs baseline: 1.4350x; 1.3803x over previous
#include <cuda_runtime.h>
#include <cuda_fp16.h>
#include <cstdint>

#define Tt 3
#define Ll 4
#define Mm 3
#define Bb 8
#define Cc 64
#define Hh 128
#define Ww 128
#define HWp (Hh*Ww)
#define PW 130
#define PPX (PW*PW)              // 16900 padded pixels
#define FRONT 256
#define SLACK 384
#define PTOT (FRONT + PPX + SLACK)

#define TILE_M 256
#define HALO 131                 // PW + 1
#define STRIP_PX (TILE_M + 2*HALO)   // 518
#define STRIP_B (STRIP_PX*128)       // 66304 bytes per half
#define TILES 67                 // ceil(PPX/TILE_M)
#define CTAS 148
#define JOBS (Tt*Bb*TILES)       // 1608 jobs per layer

#define SW_OFF 0                 // weights: 9 taps x 8192 B = 73728
#define SAH_OFF 73728            // A hi strip: 66304 B
#define SAL_OFF (SAH_OFF + STRIP_B)  // 140032
#define DBUF_OFF (SAL_OFF + STRIP_B) // 206336
#define SMEM_TOT (DBUF_OFF + 6144)   // 212480

// ---------------- device state ----------------
__device__ int g_sel[Tt*Ll];
// weights fp16: [mod 12][tap 9][oc 64][ic 64]
__device__ __align__(256) __half g_wH[(size_t)12*9*64*64];
// layer-0 input, padded NHWC fp16: [half][b][PTOT][64]
__device__ __align__(256) __half g_xp[2][(size_t)Bb*PTOT*Cc];
// ping-pong activations: [pp 2][half 2][t*b 24][PTOT][64]
__device__ __align__(256) __half g_act[2][2][(size_t)Tt*Bb*PTOT*Cc];

// ---------------- helpers ----------------
__device__ __forceinline__ uint32_t smem_u32(const void* p) {
    uint32_t a;
    asm("{ .reg .u64 t; cvta.to.shared.u64 t, %1; cvt.u32.u64 %0, t; }" : "=r"(a) : "l"(p));
    return a;
}
__device__ __forceinline__ void cp16(uint32_t sdst, const void* gsrc) {
    asm volatile("cp.async.cg.shared.global [%0], [%1], 16;" :: "r"(sdst), "l"(gsrc) : "memory");
}
__device__ __forceinline__ void cp_commit() { asm volatile("cp.async.commit_group;" ::: "memory"); }
template <int N>
__device__ __forceinline__ void cp_wait() {
    asm volatile("cp.async.wait_group %0;" :: "n"(N) : "memory");
}

__device__ __forceinline__ void ldmx4(uint32_t* r, uint32_t addr) {
    asm volatile("ldmatrix.sync.aligned.m8n8.x4.shared.b16 {%0,%1,%2,%3}, [%4];"
                 : "=r"(r[0]), "=r"(r[1]), "=r"(r[2]), "=r"(r[3]) : "r"(addr));
}
__device__ __forceinline__ void mma16816(float* c, const uint32_t* a, const uint32_t* b) {
    asm volatile("mma.sync.aligned.m16n8k16.row.col.f32.f16.f16.f32 "
                 "{%0,%1,%2,%3}, {%4,%5,%6,%7}, {%8,%9}, {%0,%1,%2,%3};"
                 : "+f"(c[0]), "+f"(c[1]), "+f"(c[2]), "+f"(c[3])
                 : "r"(a[0]), "r"(a[1]), "r"(a[2]), "r"(a[3]), "r"(b[0]), "r"(b[1]));
}
// packed hi/lo fp16 split: f0,f1 -> hw (fp16x2), lw (fp16x2 of residuals)
__device__ __forceinline__ void split2(float f0, float f1, uint32_t& hw, uint32_t& lw) {
    __half h0 = __float2half_rn(f0), h1 = __float2half_rn(f1);
    float l0 = f0 - __half2float(h0);
    float l1 = f1 - __half2float(h1);
    __half g0 = __float2half_rn(l0), g1 = __float2half_rn(l1);
    hw = ((uint32_t)__half_as_ushort(h1) << 16) | __half_as_ushort(h0);
    lw = ((uint32_t)__half_as_ushort(g1) << 16) | __half_as_ushort(g0);
}

// ---------------- fused prep kernel ----------------------------------------
__global__ void __launch_bounds__(256) prep_kernel(
    const float* __restrict__ x, const float* __restrict__ alpha0,
    const float* __restrict__ alphas, const float* __restrict__ g0,
    const float* __restrict__ gs, const float* __restrict__ enc_w)
{
    const int bid = blockIdx.x;
    const int tid = threadIdx.x;

    if (bid < 128) {
        // ---- xprep: NCHW fp32 -> padded NHWC fp16 hi/lo, 4 px per thread ----
        int idx = bid * 256 + tid;            // [0, 32768)
        int b = idx >> 12;
        int pg = idx & 4095;
        int px0 = pg * 4;
        int y = px0 >> 7, x0 = px0 & 127;
        int p0 = (y + 1) * PW + (x0 + 1);
        const float* xs = x + ((size_t)b * Cc << 14) + px0;
        __half* dh = g_xp[0] + ((size_t)b * PTOT + FRONT + p0) * Cc;
        __half* dl = g_xp[1] + ((size_t)b * PTOT + FRONT + p0) * Cc;
        #pragma unroll
        for (int g = 0; g < 8; g++) {
            float4 v[8];
            #pragma unroll
            for (int j = 0; j < 8; j++)
                v[j] = *reinterpret_cast<const float4*>(xs + (size_t)(g*8 + j) * HWp);
            #pragma unroll
            for (int e = 0; e < 4; e++) {
                uint32_t hv[4], lv[4];
                #pragma unroll
                for (int q = 0; q < 4; q++) {
                    float f0 = (&v[q*2].x)[e];
                    float f1 = (&v[q*2+1].x)[e];
                    split2(f0, f1, hv[q], lv[q]);
                }
                *reinterpret_cast<uint4*>(dh + (size_t)e * Cc + g*8) =
                    make_uint4(hv[0], hv[1], hv[2], hv[3]);
                *reinterpret_cast<uint4*>(dl + (size_t)e * Cc + g*8) =
                    make_uint4(lv[0], lv[1], lv[2], lv[3]);
            }
        }
    } else if (bid < 1856) {
        // ---- wprep: OIHW fp32 -> [mod][tap][oc][ic] fp16 ----
        int i = (bid - 128) * 256 + tid;       // [0, 442368)
        int ic  = i & 63;
        int oc  = (i >> 6) & 63;
        int tap = (i >> 12) % 9;
        int mod = i / 36864;
        float w = enc_w[(((size_t)(mod*Cc + oc))*Cc + ic)*9 + tap];
        g_wH[(((size_t)mod*9 + tap)*64 + oc)*64 + ic] = __float2half_rn(w);
    } else if (bid < 2362) {
        // ---- zero border pixels of all 112 padded planes ----
        int item = (bid - 1856) * 256 + tid;
        if (item >= 112 * 1156) return;
        int plane = item / 1156;
        int bi = item - plane * 1156;
        int px;
        if (bi < 256) px = bi;
        else {
            bi -= 256;
            if (bi < 130) px = FRONT + bi;
            else {
                bi -= 130;
                if (bi < 256) { int r = bi >> 1, c = bi & 1; px = FRONT + (r+1)*PW + c*129; }
                else {
                    bi -= 256;
                    if (bi < 130) px = FRONT + 129*PW + bi;
                    else px = FRONT + PPX + (bi - 130);
                }
            }
        }
        __half* base;
        if (plane < 16) base = g_xp[plane >> 3] + (size_t)(plane & 7) * PTOT * Cc;
        else {
            int k = plane - 16; int arr = k / 24; int img = k % 24;
            base = g_act[arr >> 1][arr & 1] + (size_t)img * PTOT * Cc;
        }
        uint4 z = make_uint4(0, 0, 0, 0);
        uint4* d = (uint4*)(base + (size_t)px * Cc);
        #pragma unroll
        for (int q = 0; q < 8; q++) d[q] = z;
    } else {
        // ---- routing ----
        int t = tid;
        if (t >= Tt) return;
        int idx = 0;
        {
            float best = -1e30f; int bi2 = 0;
            #pragma unroll
            for (int m = 0; m < Mm; m++) {
                float v = alpha0[t*Mm + m] + g0[t*Mm + m];
                if (v > best) { best = v; bi2 = m; }
            }
            idx = bi2; g_sel[t*Ll + 0] = bi2;
        }
        for (int l = 1; l < Ll; l++) {
            const float* a = alphas + ((((size_t)(l-1)*Tt + t)*Mm + idx)*Mm);
            const float* g = gs     + ((((size_t)(l-1)*Tt + t)*Mm + idx)*Mm);
            float best = -1e30f; int bi2 = 0;
            #pragma unroll
            for (int m = 0; m < Mm; m++) {
                float v = a[m] + g[m];
                if (v > best) { best = v; bi2 = m; }
            }
            idx = bi2; g_sel[t*Ll + l] = bi2;
        }
    }
}

// ---------------- conv pass: 9 taps x 4 k of m16n8k16, 2-term fp16 ---------
__device__ __forceinline__ void conv_pass(float (*acc)[4][4], uint32_t sb,
                                          int lane, int wm, int wn) {
    const int arow = lane & 15;
    const int akhalf = (lane >> 4) * 16;
    const int ocl = (lane & 7) + ((lane >> 4) << 3);
    const int bkhalf = ((lane >> 3) & 1) * 16;

    int obase[2], oxor[2];
    #pragma unroll
    for (int pr = 0; pr < 2; pr++) {
        int oc = wn * 32 + pr * 16 + ocl;
        obase[pr] = oc * 128;
        oxor[pr] = (oc & 7) << 4;
    }

    #pragma unroll
    for (int tap = 0; tap < 9; tap++) {
        const int dy = tap / 3 - 1, dx = tap % 3 - 1;
        const int pxoff = HALO + dy * PW + dx;
        const uint32_t bb = sb + SW_OFF + tap * 8192;

        int abase[4], axor[4];
        #pragma unroll
        for (int mt = 0; mt < 4; mt++) {
            int px = wm * 64 + mt * 16 + arow + pxoff;
            abase[mt] = px * 128;
            axor[mt] = (px & 7) << 4;
        }

        #pragma unroll
        for (int k = 0; k < 4; k++) {
            uint32_t bh[4][2];
            #pragma unroll
            for (int pr = 0; pr < 2; pr++) {
                uint32_t off = obase[pr] + (uint32_t)((k * 32 + bkhalf) ^ oxor[pr]);
                uint32_t r[4];
                ldmx4(r, bb + off);
                bh[pr*2][0] = r[0]; bh[pr*2][1] = r[1];
                bh[pr*2+1][0] = r[2]; bh[pr*2+1][1] = r[3];
            }
            uint32_t aH[4][4], aL[4][4];
            #pragma unroll
            for (int mt = 0; mt < 4; mt++) {
                uint32_t off = abase[mt] + (uint32_t)((k * 32 + akhalf) ^ axor[mt]);
                ldmx4(aH[mt], sb + SAH_OFF + off);
                ldmx4(aL[mt], sb + SAL_OFF + off);
            }
            #pragma unroll
            for (int mt = 0; mt < 4; mt++)
                #pragma unroll
                for (int nt = 0; nt < 4; nt++)
                    mma16816(acc[mt][nt], aH[mt], bh[nt]);
            #pragma unroll
            for (int mt = 0; mt < 4; mt++)
                #pragma unroll
                for (int nt = 0; nt < 4; nt++)
                    mma16816(acc[mt][nt], aL[mt], bh[nt]);
        }
    }
}

// ---------------- conv layer kernel ----------------------------------------
__global__ void __launch_bounds__(256) conv_hmma(
    int layer, int l0, int ps, int pd,
    const float* __restrict__ enc_b,
    const float* __restrict__ dec_w, const float* __restrict__ dec_b,
    float* __restrict__ out)
{
    extern __shared__ __align__(1024) char smem[];
    const uint32_t sb = smem_u32(smem);
    float (*dbuf)[2][3] = (float (*)[2][3])(smem + DBUF_OFF);
    const int tid = threadIdx.x;
    const int lane = tid & 31, wid = tid >> 5;
    const int wm = wid >> 1, wn = wid & 1;
    const int cta = blockIdx.x;

    const int nj = (cta < 128) ? 11 : 10;
    int j = (cta < 128) ? cta * 11 : 128 * 11 + (cta - 128) * 10;

    auto src_half = [&](int half, int img) -> const char* {
        const __half* p;
        if (l0) p = g_xp[half] + ((size_t)(img & 7) * PTOT + FRONT) * Cc;
        else    p = g_act[ps][half] + ((size_t)img * PTOT + FRONT) * Cc;
        return (const char*)p;
    };
    // stage full 64-ic strip (66304 B) to dst_off
    auto stage = [&](const char* src, int tb, uint32_t dst_off) {
        const char* g = src + (size_t)(tb - HALO) * 128;
        for (int i = tid; i < STRIP_PX * 8; i += 256) {
            int px = i >> 3;
            int c = (i & 7) << 4;
            uint32_t sw = (uint32_t)(px * 128 + (c ^ ((px & 7) << 4)));
            cp16(sb + dst_off + sw, g + (size_t)px * 128 + c);
        }
    };
    auto stage_w = [&](int mod) {
        const char* wsrc = (const char*)g_wH + (size_t)mod * 73728;
        for (int g = tid; g < 4608; g += 256) {
            int o = g * 16;
            int sw = o ^ ((o >> 3) & 0x70);
            cp16(sb + SW_OFF + sw, wsrc + o);
        }
    };

    // prologue: weights + A(h,l) of first tile
    {
        const int img0 = j / TILES;
        const int tile0 = j - img0 * TILES;
        const int t0 = img0 >> 3;
        stage_w(layer * Mm + g_sel[t0*Ll + layer]);
        stage(src_half(0, img0), tile0 * TILE_M, SAH_OFF);
        stage(src_half(1, img0), tile0 * TILE_M, SAL_OFF);
        cp_commit();
    }
    int cur_mod_t = (j / TILES) >> 3;

    for (int jj = 0; jj < nj; jj++, j++) {
        const int img = j / TILES;
        const int tile = j - img * TILES;
        const int t = img >> 3;
        const int tb = tile * TILE_M;
        const int mod = layer * Mm + g_sel[t*Ll + layer];

        bool has_next = (jj + 1 < nj);
        int t2 = 0;
        bool mod_sw = false;
        const char* nH = nullptr; const char* nL = nullptr;
        int ntb = 0;
        if (has_next) {
            int j2 = j + 1;
            int img2 = j2 / TILES;
            ntb = (j2 - img2 * TILES) * TILE_M;
            t2 = img2 >> 3;
            mod_sw = (t2 != cur_mod_t) &&
                     (g_sel[t2*Ll + layer] != g_sel[cur_mod_t*Ll + layer]);
            nH = src_half(0, img2);
            nL = src_half(1, img2);
        }

        float acc[4][4][4];
        #pragma unroll
        for (int mt = 0; mt < 4; mt++)
            #pragma unroll
            for (int nt = 0; nt < 4; nt++)
                #pragma unroll
                for (int r = 0; r < 4; r++) acc[mt][nt][r] = 0.f;

        cp_wait<0>();
        __syncthreads();                 // A(h,l) + weights ready

        conv_pass(acc, sb, lane, wm, wn);

        __syncthreads();                 // all warps done reading A + weights

        if (has_next) {
            stage(nH, ntb, SAH_OFF);     // next A — hidden under epilogue+entry
            stage(nL, ntb, SAL_OFF);
            if (mod_sw) stage_w(layer * Mm + g_sel[t2*Ll + layer]);
            cp_commit();
        }

        const int g = lane >> 2, c2 = (lane & 3) * 2;
        const float* bb = enc_b + mod * 64;

        if (layer != 3) {
            __half* dst_h = g_act[pd][0] + ((size_t)img * PTOT + FRONT) * Cc;
            __half* dst_l = g_act[pd][1] + ((size_t)img * PTOT + FRONT) * Cc;
            #pragma unroll
            for (int mt = 0; mt < 4; mt++) {
                #pragma unroll
                for (int r = 0; r < 2; r++) {
                    int row = wm * 64 + mt * 16 + g + r * 8;
                    int p = tb + row;
                    if (p < PPX) {
                        int y = p / PW, xx = p - y * PW;
                        if (y >= 1 && y <= Hh && xx >= 1 && xx <= Ww) {
                            size_t base = (size_t)p * Cc;
                            #pragma unroll
                            for (int nt = 0; nt < 4; nt++) {
                                int oc = wn * 32 + nt * 8 + c2;
                                float f0 = fmaxf(acc[mt][nt][r*2+0] + __ldg(bb + oc),     0.f);
                                float f1 = fmaxf(acc[mt][nt][r*2+1] + __ldg(bb + oc + 1), 0.f);
                                uint32_t hw, lw;
                                split2(f0, f1, hw, lw);
                                *(uint32_t*)(dst_h + base + oc) = hw;
                                *(uint32_t*)(dst_l + base + oc) = lw;
                            }
                        }
                    }
                }
            }
        } else {
            // fused decoder
            float wd[3][8];
            #pragma unroll
            for (int kk = 0; kk < 3; kk++)
                #pragma unroll
                for (int q = 0; q < 8; q++) {
                    int oc = wn * 32 + (q >> 1) * 8 + c2 + (q & 1);
                    wd[kk][q] = __ldg(dec_w + ((size_t)t * 3 + kk) * 64 + oc);
                }
            #pragma unroll
            for (int mt = 0; mt < 4; mt++) {
                #pragma unroll
                for (int r = 0; r < 2; r++) {
                    float p0 = 0.f, p1 = 0.f, p2 = 0.f;
                    #pragma unroll
                    for (int nt = 0; nt < 4; nt++) {
                        int oc = wn * 32 + nt * 8 + c2;
                        float f0 = fmaxf(acc[mt][nt][r*2+0] + __ldg(bb + oc),     0.f);
                        float f1 = fmaxf(acc[mt][nt][r*2+1] + __ldg(bb + oc + 1), 0.f);
                        p0 = fmaf(f0, wd[0][nt*2+0], fmaf(f1, wd[0][nt*2+1], p0));
                        p1 = fmaf(f0, wd[1][nt*2+0], fmaf(f1, wd[1][nt*2+1], p1));
                        p2 = fmaf(f0, wd[2][nt*2+0], fmaf(f1, wd[2][nt*2+1], p2));
                    }
                    #pragma unroll
                    for (int off = 1; off < 4; off <<= 1) {
                        p0 += __shfl_xor_sync(0xffffffffu, p0, off);
                        p1 += __shfl_xor_sync(0xffffffffu, p1, off);
                        p2 += __shfl_xor_sync(0xffffffffu, p2, off);
                    }
                    if ((lane & 3) == 0) {
                        int pix = wm * 64 + mt * 16 + r * 8 + g;
                        dbuf[pix][wn][0] = p0;
                        dbuf[pix][wn][1] = p1;
                        dbuf[pix][wn][2] = p2;
                    }
                }
            }
            __syncthreads();
            {
                int p = tb + tid;
                if (p < PPX) {
                    int y = p / PW, xx = p - y * PW;
                    if (y >= 1 && y <= Hh && xx >= 1 && xx <= Ww) {
                        float a0 = dbuf[tid][0][0] + dbuf[tid][1][0] + __ldg(dec_b + t*3 + 0);
                        float a1 = dbuf[tid][0][1] + dbuf[tid][1][1] + __ldg(dec_b + t*3 + 1);
                        float a2 = dbuf[tid][0][2] + dbuf[tid][1][2] + __ldg(dec_b + t*3 + 2);
                        if (t == 2) {
                            float n = rsqrtf(a0*a0 + a1*a1 + a2*a2);
                            a0 *= n; a1 *= n; a2 *= n;
                        }
                        float* op = out + ((size_t)img * 3) * HWp + (y - 1) * Ww + (xx - 1);
                        op[0] = a0;
                        op[HWp] = a1;
                        op[2*HWp] = a2;
                    }
                }
            }
        }

        if (has_next) cur_mod_t = t2;
    }
}

extern "C" void kernel_launch(void* const* d_in, const int* in_sizes, int n_in,
                              void* d_out, int out_size) {
    const float* x      = (const float*)d_in[0];
    const float* alpha0 = (const float*)d_in[1];
    const float* alphas = (const float*)d_in[2];
    const float* g0     = (const float*)d_in[3];
    const float* gs     = (const float*)d_in[4];
    const float* enc_w  = (const float*)d_in[5];
    const float* enc_b  = (const float*)d_in[6];
    const float* dec_w  = (const float*)d_in[7];
    const float* dec_b  = (const float*)d_in[8];
    float* out = (float*)d_out;

    cudaFuncSetAttribute(conv_hmma, cudaFuncAttributeMaxDynamicSharedMemorySize, SMEM_TOT);

    prep_kernel<<<2363, 256>>>(x, alpha0, alphas, g0, gs, enc_w);

    conv_hmma<<<CTAS, 256, SMEM_TOT>>>(0, 1, 0, 0, enc_b, dec_w, dec_b, out);
    conv_hmma<<<CTAS, 256, SMEM_TOT>>>(1, 0, 0, 1, enc_b, dec_w, dec_b, out);
    conv_hmma<<<CTAS, 256, SMEM_TOT>>>(2, 0, 1, 0, enc_b, dec_w, dec_b, out);
    conv_hmma<<<CTAS, 256, SMEM_TOT>>>(3, 0, 0, 1, enc_b, dec_w, dec_b, out);
}

// round 10
// speedup vs baseline: 2.7076x; 1.8868x over previous
#include <cuda_runtime.h>
#include <cuda_fp16.h>
#include <cstdint>

#define Tt 3
#define Ll 4
#define Mm 3
#define Bb 8
#define Cc 64
#define Hh 128
#define Ww 128
#define HWp (Hh*Ww)
#define PW 130
#define PPX (PW*PW)              // 16900 padded pixels
#define FRONT 256
#define SLACK 384
#define PTOT (FRONT + PPX + SLACK)

#define TILE_M 256
#define HALO 131                 // PW + 1
#define STRIP_PX (TILE_M + 2*HALO)   // 518
#define STRIP_B (STRIP_PX*128)       // 66304 bytes
#define TILES 67                 // ceil(PPX/TILE_M)
#define CTAS 148
#define JOBS (Tt*Bb*TILES)       // 1608 jobs per layer

#define SW_OFF 0                 // weights: 9 taps x 8192 B = 73728
#define SA0_OFF 73728            // A buffer 0: 66304 B
#define SA1_OFF (SA0_OFF + STRIP_B)  // 140032
#define DBUF_OFF (SA1_OFF + STRIP_B) // 206336
#define SMEM_TOT (DBUF_OFF + 6144)   // 212480

// ---------------- device state ----------------
__device__ int g_sel[Tt*Ll];
// weights fp16: [mod 12][tap 9][oc 64][ic 64]
__device__ __align__(256) __half g_wH[(size_t)12*9*64*64];
// layer-0 input, padded NHWC fp16: [b][PTOT][64]
__device__ __align__(256) __half g_xp[(size_t)Bb*PTOT*Cc];
// ping-pong activations: [pp 2][t*b 24][PTOT][64]
__device__ __align__(256) __half g_act[2][(size_t)Tt*Bb*PTOT*Cc];

// ---------------- helpers ----------------
__device__ __forceinline__ uint32_t smem_u32(const void* p) {
    uint32_t a;
    asm("{ .reg .u64 t; cvta.to.shared.u64 t, %1; cvt.u32.u64 %0, t; }" : "=r"(a) : "l"(p));
    return a;
}
__device__ __forceinline__ void cp16(uint32_t sdst, const void* gsrc) {
    asm volatile("cp.async.cg.shared.global [%0], [%1], 16;" :: "r"(sdst), "l"(gsrc) : "memory");
}
__device__ __forceinline__ void cp_commit() { asm volatile("cp.async.commit_group;" ::: "memory"); }
template <int N>
__device__ __forceinline__ void cp_wait() {
    asm volatile("cp.async.wait_group %0;" :: "n"(N) : "memory");
}

__device__ __forceinline__ void ldmx4(uint32_t* r, uint32_t addr) {
    asm volatile("ldmatrix.sync.aligned.m8n8.x4.shared.b16 {%0,%1,%2,%3}, [%4];"
                 : "=r"(r[0]), "=r"(r[1]), "=r"(r[2]), "=r"(r[3]) : "r"(addr));
}
__device__ __forceinline__ void mma16816(float* c, const uint32_t* a, const uint32_t* b) {
    asm volatile("mma.sync.aligned.m16n8k16.row.col.f32.f16.f16.f32 "
                 "{%0,%1,%2,%3}, {%4,%5,%6,%7}, {%8,%9}, {%0,%1,%2,%3};"
                 : "+f"(c[0]), "+f"(c[1]), "+f"(c[2]), "+f"(c[3])
                 : "r"(a[0]), "r"(a[1]), "r"(a[2]), "r"(a[3]), "r"(b[0]), "r"(b[1]));
}

// ---------------- fused prep kernel ----------------------------------------
// blocks [0,128): xprep; [128,1856): wprep; [1856,2109): border zero; 2109: routing
__global__ void __launch_bounds__(256) prep_kernel(
    const float* __restrict__ x, const float* __restrict__ alpha0,
    const float* __restrict__ alphas, const float* __restrict__ g0,
    const float* __restrict__ gs, const float* __restrict__ enc_w)
{
    const int bid = blockIdx.x;
    const int tid = threadIdx.x;

    if (bid < 128) {
        // ---- xprep: NCHW fp32 -> padded NHWC fp16, 4 px per thread ----
        int idx = bid * 256 + tid;            // [0, 32768)
        int b = idx >> 12;
        int pg = idx & 4095;
        int px0 = pg * 4;
        int y = px0 >> 7, x0 = px0 & 127;
        int p0 = (y + 1) * PW + (x0 + 1);
        const float* xs = x + ((size_t)b * Cc << 14) + px0;
        __half* dh = g_xp + ((size_t)b * PTOT + FRONT + p0) * Cc;
        #pragma unroll
        for (int g = 0; g < 8; g++) {
            float4 v[8];
            #pragma unroll
            for (int j = 0; j < 8; j++)
                v[j] = *reinterpret_cast<const float4*>(xs + (size_t)(g*8 + j) * HWp);
            #pragma unroll
            for (int e = 0; e < 4; e++) {
                uint32_t hv[4];
                #pragma unroll
                for (int q = 0; q < 4; q++) {
                    __half2 h = __floats2half2_rn((&v[q*2].x)[e], (&v[q*2+1].x)[e]);
                    hv[q] = *reinterpret_cast<uint32_t*>(&h);
                }
                *reinterpret_cast<uint4*>(dh + (size_t)e * Cc + g*8) =
                    make_uint4(hv[0], hv[1], hv[2], hv[3]);
            }
        }
    } else if (bid < 1856) {
        // ---- wprep: OIHW fp32 -> [mod][tap][oc][ic] fp16 ----
        int i = (bid - 128) * 256 + tid;       // [0, 442368)
        int ic  = i & 63;
        int oc  = (i >> 6) & 63;
        int tap = (i >> 12) % 9;
        int mod = i / 36864;
        float w = enc_w[(((size_t)(mod*Cc + oc))*Cc + ic)*9 + tap];
        g_wH[(((size_t)mod*9 + tap)*64 + oc)*64 + ic] = __float2half_rn(w);
    } else if (bid < 2109) {
        // ---- zero border pixels of 56 padded planes (8 xp + 48 act) ----
        int item = (bid - 1856) * 256 + tid;
        if (item >= 56 * 1156) return;
        int plane = item / 1156;
        int bi = item - plane * 1156;
        int px;
        if (bi < 256) px = bi;
        else {
            bi -= 256;
            if (bi < 130) px = FRONT + bi;
            else {
                bi -= 130;
                if (bi < 256) { int r = bi >> 1, c = bi & 1; px = FRONT + (r+1)*PW + c*129; }
                else {
                    bi -= 256;
                    if (bi < 130) px = FRONT + 129*PW + bi;
                    else px = FRONT + PPX + (bi - 130);
                }
            }
        }
        __half* base;
        if (plane < 8) base = g_xp + (size_t)plane * PTOT * Cc;
        else {
            int k = plane - 8;
            base = g_act[k / 24] + (size_t)(k % 24) * PTOT * Cc;
        }
        uint4 z = make_uint4(0, 0, 0, 0);
        uint4* d = (uint4*)(base + (size_t)px * Cc);
        #pragma unroll
        for (int q = 0; q < 8; q++) d[q] = z;
    } else {
        // ---- routing ----
        int t = tid;
        if (t >= Tt) return;
        int idx = 0;
        {
            float best = -1e30f; int bi2 = 0;
            #pragma unroll
            for (int m = 0; m < Mm; m++) {
                float v = alpha0[t*Mm + m] + g0[t*Mm + m];
                if (v > best) { best = v; bi2 = m; }
            }
            idx = bi2; g_sel[t*Ll + 0] = bi2;
        }
        for (int l = 1; l < Ll; l++) {
            const float* a = alphas + ((((size_t)(l-1)*Tt + t)*Mm + idx)*Mm);
            const float* g = gs     + ((((size_t)(l-1)*Tt + t)*Mm + idx)*Mm);
            float best = -1e30f; int bi2 = 0;
            #pragma unroll
            for (int m = 0; m < Mm; m++) {
                float v = a[m] + g[m];
                if (v > best) { best = v; bi2 = m; }
            }
            idx = bi2; g_sel[t*Ll + l] = bi2;
        }
    }
}

// ---------------- conv pass: 9 taps x 4 k of m16n8k16, 1-term fp16 ---------
__device__ __forceinline__ void conv_pass(float (*acc)[4][4], uint32_t sb,
                                          uint32_t abuf, int lane, int wm, int wn) {
    const int arow = lane & 15;
    const int akhalf = (lane >> 4) * 16;
    const int ocl = (lane & 7) + ((lane >> 4) << 3);
    const int bkhalf = ((lane >> 3) & 1) * 16;

    int obase[2], oxor[2];
    #pragma unroll
    for (int pr = 0; pr < 2; pr++) {
        int oc = wn * 32 + pr * 16 + ocl;
        obase[pr] = oc * 128;
        oxor[pr] = (oc & 7) << 4;
    }

    #pragma unroll
    for (int tap = 0; tap < 9; tap++) {
        const int dy = tap / 3 - 1, dx = tap % 3 - 1;
        const int pxoff = HALO + dy * PW + dx;
        const uint32_t bb = sb + SW_OFF + tap * 8192;

        int abase[4], axor[4];
        #pragma unroll
        for (int mt = 0; mt < 4; mt++) {
            int px = wm * 64 + mt * 16 + arow + pxoff;
            abase[mt] = px * 128;
            axor[mt] = (px & 7) << 4;
        }

        #pragma unroll
        for (int k = 0; k < 4; k++) {
            uint32_t bh[4][2];
            #pragma unroll
            for (int pr = 0; pr < 2; pr++) {
                uint32_t off = obase[pr] + (uint32_t)((k * 32 + bkhalf) ^ oxor[pr]);
                uint32_t r[4];
                ldmx4(r, bb + off);
                bh[pr*2][0] = r[0]; bh[pr*2][1] = r[1];
                bh[pr*2+1][0] = r[2]; bh[pr*2+1][1] = r[3];
            }
            uint32_t aF[4][4];
            #pragma unroll
            for (int mt = 0; mt < 4; mt++) {
                uint32_t off = abase[mt] + (uint32_t)((k * 32 + akhalf) ^ axor[mt]);
                ldmx4(aF[mt], abuf + off);
            }
            #pragma unroll
            for (int mt = 0; mt < 4; mt++)
                #pragma unroll
                for (int nt = 0; nt < 4; nt++)
                    mma16816(acc[mt][nt], aF[mt], bh[nt]);
        }
    }
}

// ---------------- conv layer kernel ----------------------------------------
__global__ void __launch_bounds__(256) conv_hmma(
    int layer, int l0, int ps, int pd,
    const float* __restrict__ enc_b,
    const float* __restrict__ dec_w, const float* __restrict__ dec_b,
    float* __restrict__ out)
{
    extern __shared__ __align__(1024) char smem[];
    const uint32_t sb = smem_u32(smem);
    float (*dbuf)[2][3] = (float (*)[2][3])(smem + DBUF_OFF);
    const int tid = threadIdx.x;
    const int lane = tid & 31, wid = tid >> 5;
    const int wm = wid >> 1, wn = wid & 1;
    const int cta = blockIdx.x;

    const int nj = (cta < 128) ? 11 : 10;
    int j = (cta < 128) ? cta * 11 : 128 * 11 + (cta - 128) * 10;

    auto src = [&](int img) -> const char* {
        const __half* p;
        if (l0) p = g_xp + ((size_t)(img & 7) * PTOT + FRONT) * Cc;
        else    p = g_act[ps] + ((size_t)img * PTOT + FRONT) * Cc;
        return (const char*)p;
    };
    // stage full 64-ic strip (66304 B) to dst_off
    auto stage = [&](const char* s, int tb, uint32_t dst_off) {
        const char* g = s + (size_t)(tb - HALO) * 128;
        for (int i = tid; i < STRIP_PX * 8; i += 256) {
            int px = i >> 3;
            int c = (i & 7) << 4;
            uint32_t sw = (uint32_t)(px * 128 + (c ^ ((px & 7) << 4)));
            cp16(sb + dst_off + sw, g + (size_t)px * 128 + c);
        }
    };
    auto stage_w = [&](int mod) {
        const char* wsrc = (const char*)g_wH + (size_t)mod * 73728;
        for (int g = tid; g < 4608; g += 256) {
            int o = g * 16;
            int sw = o ^ ((o >> 3) & 0x70);
            cp16(sb + SW_OFF + sw, wsrc + o);
        }
    };

    // prologue: weights + A of first tile into buf0
    {
        const int img0 = j / TILES;
        const int tile0 = j - img0 * TILES;
        const int t0 = img0 >> 3;
        stage_w(layer * Mm + g_sel[t0*Ll + layer]);
        stage(src(img0), tile0 * TILE_M, SA0_OFF);
        cp_commit();
    }
    int cur_mod_t = (j / TILES) >> 3;

    for (int jj = 0; jj < nj; jj++, j++) {
        const int img = j / TILES;
        const int tile = j - img * TILES;
        const int t = img >> 3;
        const int tb = tile * TILE_M;
        const int mod = layer * Mm + g_sel[t*Ll + layer];
        const uint32_t abuf = sb + ((jj & 1) ? SA1_OFF : SA0_OFF);

        bool has_next = (jj + 1 < nj);
        int t2 = 0;
        bool mod_sw = false;
        if (has_next) {
            int j2 = j + 1;
            int img2 = j2 / TILES;
            int ntb = (j2 - img2 * TILES) * TILE_M;
            t2 = img2 >> 3;
            mod_sw = (t2 != cur_mod_t) &&
                     (g_sel[t2*Ll + layer] != g_sel[cur_mod_t*Ll + layer]);
            // entry wait below guarantees prior groups landed; buffer jj^1 was
            // last read in tile jj-1, and all warps passed the entry sync of
            // tile jj before we write it here.
            cp_wait<0>();
            __syncthreads();                 // A(cur) + weights ready; buf(next) free
            stage(src(img2), ntb, (jj & 1) ? SA0_OFF : SA1_OFF);
            cp_commit();
        } else {
            cp_wait<0>();
            __syncthreads();
        }

        float acc[4][4][4];
        #pragma unroll
        for (int mt = 0; mt < 4; mt++)
            #pragma unroll
            for (int nt = 0; nt < 4; nt++)
                #pragma unroll
                for (int r = 0; r < 4; r++) acc[mt][nt][r] = 0.f;

        conv_pass(acc, sb, abuf, lane, wm, wn);

        const int g = lane >> 2, c2 = (lane & 3) * 2;
        const float* bb = enc_b + mod * 64;

        if (layer != 3) {
            __half* dst = g_act[pd] + ((size_t)img * PTOT + FRONT) * Cc;
            #pragma unroll
            for (int mt = 0; mt < 4; mt++) {
                #pragma unroll
                for (int r = 0; r < 2; r++) {
                    int row = wm * 64 + mt * 16 + g + r * 8;
                    int p = tb + row;
                    if (p < PPX) {
                        int y = p / PW, xx = p - y * PW;
                        if (y >= 1 && y <= Hh && xx >= 1 && xx <= Ww) {
                            size_t base = (size_t)p * Cc;
                            #pragma unroll
                            for (int nt = 0; nt < 4; nt++) {
                                int oc = wn * 32 + nt * 8 + c2;
                                float f0 = fmaxf(acc[mt][nt][r*2+0] + __ldg(bb + oc),     0.f);
                                float f1 = fmaxf(acc[mt][nt][r*2+1] + __ldg(bb + oc + 1), 0.f);
                                __half2 h = __floats2half2_rn(f0, f1);
                                *(uint32_t*)(dst + base + oc) = *reinterpret_cast<uint32_t*>(&h);
                            }
                        }
                    }
                }
            }
        } else {
            // fused decoder
            float wd[3][8];
            #pragma unroll
            for (int kk = 0; kk < 3; kk++)
                #pragma unroll
                for (int q = 0; q < 8; q++) {
                    int oc = wn * 32 + (q >> 1) * 8 + c2 + (q & 1);
                    wd[kk][q] = __ldg(dec_w + ((size_t)t * 3 + kk) * 64 + oc);
                }
            #pragma unroll
            for (int mt = 0; mt < 4; mt++) {
                #pragma unroll
                for (int r = 0; r < 2; r++) {
                    float p0 = 0.f, p1 = 0.f, p2 = 0.f;
                    #pragma unroll
                    for (int nt = 0; nt < 4; nt++) {
                        int oc = wn * 32 + nt * 8 + c2;
                        float f0 = fmaxf(acc[mt][nt][r*2+0] + __ldg(bb + oc),     0.f);
                        float f1 = fmaxf(acc[mt][nt][r*2+1] + __ldg(bb + oc + 1), 0.f);
                        p0 = fmaf(f0, wd[0][nt*2+0], fmaf(f1, wd[0][nt*2+1], p0));
                        p1 = fmaf(f0, wd[1][nt*2+0], fmaf(f1, wd[1][nt*2+1], p1));
                        p2 = fmaf(f0, wd[2][nt*2+0], fmaf(f1, wd[2][nt*2+1], p2));
                    }
                    #pragma unroll
                    for (int off = 1; off < 4; off <<= 1) {
                        p0 += __shfl_xor_sync(0xffffffffu, p0, off);
                        p1 += __shfl_xor_sync(0xffffffffu, p1, off);
                        p2 += __shfl_xor_sync(0xffffffffu, p2, off);
                    }
                    if ((lane & 3) == 0) {
                        int pix = wm * 64 + mt * 16 + r * 8 + g;
                        dbuf[pix][wn][0] = p0;
                        dbuf[pix][wn][1] = p1;
                        dbuf[pix][wn][2] = p2;
                    }
                }
            }
            __syncthreads();
            {
                int p = tb + tid;
                if (p < PPX) {
                    int y = p / PW, xx = p - y * PW;
                    if (y >= 1 && y <= Hh && xx >= 1 && xx <= Ww) {
                        float a0 = dbuf[tid][0][0] + dbuf[tid][1][0] + __ldg(dec_b + t*3 + 0);
                        float a1 = dbuf[tid][0][1] + dbuf[tid][1][1] + __ldg(dec_b + t*3 + 1);
                        float a2 = dbuf[tid][0][2] + dbuf[tid][1][2] + __ldg(dec_b + t*3 + 2);
                        if (t == 2) {
                            float n = rsqrtf(a0*a0 + a1*a1 + a2*a2);
                            a0 *= n; a1 *= n; a2 *= n;
                        }
                        float* op = out + ((size_t)img * 3) * HWp + (y - 1) * Ww + (xx - 1);
                        op[0] = a0;
                        op[HWp] = a1;
                        op[2*HWp] = a2;
                    }
                }
            }
        }

        // module switch: re-stage weights after all warps done with old ones
        if (has_next && mod_sw) {
            __syncthreads();
            stage_w(layer * Mm + g_sel[t2*Ll + layer]);
            cp_commit();
        }
        if (has_next) cur_mod_t = t2;
    }
}

extern "C" void kernel_launch(void* const* d_in, const int* in_sizes, int n_in,
                              void* d_out, int out_size) {
    const float* x      = (const float*)d_in[0];
    const float* alpha0 = (const float*)d_in[1];
    const float* alphas = (const float*)d_in[2];
    const float* g0     = (const float*)d_in[3];
    const float* gs     = (const float*)d_in[4];
    const float* enc_w  = (const float*)d_in[5];
    const float* enc_b  = (const float*)d_in[6];
    const float* dec_w  = (const float*)d_in[7];
    const float* dec_b  = (const float*)d_in[8];
    float* out = (float*)d_out;

    cudaFuncSetAttribute(conv_hmma, cudaFuncAttributeMaxDynamicSharedMemorySize, SMEM_TOT);

    prep_kernel<<<2110, 256>>>(x, alpha0, alphas, g0, gs, enc_w);

    conv_hmma<<<CTAS, 256, SMEM_TOT>>>(0, 1, 0, 0, enc_b, dec_w, dec_b, out);
    conv_hmma<<<CTAS, 256, SMEM_TOT>>>(1, 0, 0, 1, enc_b, dec_w, dec_b, out);
    conv_hmma<<<CTAS, 256, SMEM_TOT>>>(2, 0, 1, 0, enc_b, dec_w, dec_b, out);
    conv_hmma<<<CTAS, 256, SMEM_TOT>>>(3, 0, 0, 1, enc_b, dec_w, dec_b, out);
}